// round 12
// baseline (speedup 1.0000x reference)
#include <cuda_runtime.h>
#include <cuda_bf16.h>
#include <cstddef>
#include <cstdint>

#define BATCH 2
#define CDIM  128
#define HH    56
#define WWD   56
#define PPOS  3136
#define LSEQ  3136
#define MR    6272
#define DI    256
#define DS    16
#define NC    49
#define CL    64

// ---------------- scratch ----------------
__device__ __align__(16) float g_xnorm[2][MR * CDIM];
__device__ __align__(16) float g_xz   [2][MR * 512];
__device__ __align__(16) float g_xs   [2][MR * DI];
__device__ __align__(16) float g_dbl  [2][MR * 40];
__device__ __align__(16) float g_dt   [2][MR * DI];
__device__ __align__(16) float g_ys   [2][MR * DI];
__device__ __align__(16) float g_o    [2][MR * CDIM];
__device__ __align__(16) float g_g    [MR * CDIM];
__device__ __align__(16) float g_lf   [MR * CDIM];
__device__ __align__(16) float g_fused[MR * CDIM];
__device__ __align__(16) float g_Pc [2][NC * BATCH * DI * DS];
__device__ __align__(16) float g_Hc [2][NC * BATCH * DI * DS];
__device__ __align__(16) float g_Hi [2][NC * BATCH * DI * DS];
__device__ __align__(16) float g_psum[BATCH * 98 * CDIM];

__device__ __forceinline__ float to_tf32(float x) {
    unsigned int u;
    asm("cvt.rna.tf32.f32 %0, %1;" : "=r"(u) : "f"(x));
    return __uint_as_float(u);
}

// ========== prep: LayerNorm (both layouts) + depthwise 3x3 + GELU ==========
__global__ __launch_bounds__(256) void prep_kernel(
    const float* __restrict__ x,
    const float* __restrict__ hw, const float* __restrict__ hb,
    const float* __restrict__ vw, const float* __restrict__ vb,
    const float* __restrict__ dww, const float* __restrict__ dwb,
    float* __restrict__ xh, float* __restrict__ xv, float* __restrict__ g)
{
    __shared__ float sx[128][33];
    __shared__ float part[8][33];
    __shared__ float partq[8][33];
    __shared__ float mu[32], rs[32];
    __shared__ float sg[128][33];
    int t = threadIdx.x;
    int p0 = blockIdx.x * 32;
    int b  = blockIdx.y;
    int pl = t & 31, c8 = t >> 5;
    float s = 0.f, sq = 0.f;
    #pragma unroll
    for (int pass = 0; pass < 16; pass++) {
        int c = pass * 8 + c8;
        float v = x[((size_t)(b * 128 + c)) * PPOS + p0 + pl];
        sx[c][pl] = v;
        s += v; sq += v * v;
    }
    part[c8][pl] = s; partq[c8][pl] = sq;
    __syncthreads();
    if (t < 32) {
        float S = 0.f, Q = 0.f;
        #pragma unroll
        for (int r = 0; r < 8; r++) { S += part[r][t]; Q += partq[r][t]; }
        float mean = S * (1.f / 128.f);
        float var  = Q * (1.f / 128.f) - mean * mean;
        mu[t] = mean;
        rs[t] = rsqrtf(var + 1e-5f);
    }
    __syncthreads();
    {
        int c = t & 127, ph = t >> 7;
        float whh = hw[c], bhh = hb[c], wvv = vw[c], bvv = vb[c];
        #pragma unroll
        for (int pass = 0; pass < 16; pass++) {
            int pl2 = pass * 2 + ph;
            int p = p0 + pl2;
            float xc = (sx[c][pl2] - mu[pl2]) * rs[pl2];
            int h = p / WWD, w = p % WWD;
            xh[((size_t)b * LSEQ + p) * 128 + c]            = xc * whh + bhh;
            xv[((size_t)b * LSEQ + (w * HH + h)) * 128 + c] = xc * wvv + bvv;
        }
    }
    {
        int p = p0 + pl;
        int h = p / WWD, w = p % WWD;
        #pragma unroll
        for (int pass = 0; pass < 16; pass++) {
            int c = pass * 8 + c8;
            const float* xb = x + ((size_t)(b * 128 + c)) * PPOS;
            float acc = dwb[c];
            #pragma unroll
            for (int kh = 0; kh < 3; kh++) {
                int hh = h + kh - 1;
                if (hh < 0 || hh >= HH) continue;
                #pragma unroll
                for (int kw = 0; kw < 3; kw++) {
                    int ww = w + kw - 1;
                    if (ww < 0 || ww >= WWD) continue;
                    acc = fmaf(xb[hh * WWD + ww], dww[c * 9 + kh * 3 + kw], acc);
                }
            }
            sg[c][pl] = 0.5f * acc * (1.f + erff(acc * 0.70710678118654752f));
        }
    }
    __syncthreads();
    {
        int c = t & 127, ph = t >> 7;
        #pragma unroll
        for (int pass = 0; pass < 16; pass++) {
            int pl2 = pass * 2 + ph;
            g[((size_t)(b * PPOS + p0 + pl2)) * 128 + c] = sg[c][pl2];
        }
    }
}

// ========== TF32 GEMM core (device func): 128x128 block, 8 warps ==========
__device__ __forceinline__ void gemm_tf32_body(
    const float* __restrict__ A, const float* __restrict__ Bw,
    const float* __restrict__ bias, float* __restrict__ C,
    int m0, int n0, int N, int K)
{
    __shared__ float As[2][8][136];
    __shared__ float Bs[2][8][136];

    const int t    = threadIdx.x;
    const int lane = t & 31;
    const int wid  = t >> 5;
    const int g    = lane >> 2;
    const int tig  = lane & 3;
    const int wm   = (wid & 1) * 64;
    const int wn   = (wid >> 1) * 32;

    const int lRow = t >> 1;
    const int lK   = (t & 1) * 4;

    const float* Aptr = A + (size_t)(m0 + lRow) * K + lK;
    const float* Bptr = Bw + (size_t)(n0 + lRow) * K + lK;

    float4 pa = *(const float4*)Aptr;
    float4 pb = *(const float4*)Bptr;

    float acc[4][4][4];
    #pragma unroll
    for (int mi = 0; mi < 4; mi++)
        #pragma unroll
        for (int ni = 0; ni < 4; ni++)
            #pragma unroll
            for (int r = 0; r < 4; r++) acc[mi][ni][r] = 0.f;

    As[0][lK + 0][lRow] = to_tf32(pa.x); As[0][lK + 1][lRow] = to_tf32(pa.y);
    As[0][lK + 2][lRow] = to_tf32(pa.z); As[0][lK + 3][lRow] = to_tf32(pa.w);
    Bs[0][lK + 0][lRow] = to_tf32(pb.x); Bs[0][lK + 1][lRow] = to_tf32(pb.y);
    Bs[0][lK + 2][lRow] = to_tf32(pb.z); Bs[0][lK + 3][lRow] = to_tf32(pb.w);
    __syncthreads();

    const int nt = K >> 3;
    int buf = 0;
    for (int kt = 0; kt < nt; kt++) {
        bool more = (kt + 1 < nt);
        if (more) {
            pa = *(const float4*)(Aptr + (kt + 1) * 8);
            pb = *(const float4*)(Bptr + (kt + 1) * 8);
        }
        unsigned int af[4][4], bf[4][2];
        #pragma unroll
        for (int mi = 0; mi < 4; mi++) {
            int rm = wm + mi * 16 + g;
            af[mi][0] = __float_as_uint(As[buf][tig][rm]);
            af[mi][1] = __float_as_uint(As[buf][tig][rm + 8]);
            af[mi][2] = __float_as_uint(As[buf][tig + 4][rm]);
            af[mi][3] = __float_as_uint(As[buf][tig + 4][rm + 8]);
        }
        #pragma unroll
        for (int ni = 0; ni < 4; ni++) {
            int cn = wn + ni * 8 + g;
            bf[ni][0] = __float_as_uint(Bs[buf][tig][cn]);
            bf[ni][1] = __float_as_uint(Bs[buf][tig + 4][cn]);
        }
        #pragma unroll
        for (int mi = 0; mi < 4; mi++)
            #pragma unroll
            for (int ni = 0; ni < 4; ni++) {
                asm volatile(
                    "mma.sync.aligned.m16n8k8.row.col.f32.tf32.tf32.f32 "
                    "{%0,%1,%2,%3}, {%4,%5,%6,%7}, {%8,%9}, {%0,%1,%2,%3};\n"
                    : "+f"(acc[mi][ni][0]), "+f"(acc[mi][ni][1]),
                      "+f"(acc[mi][ni][2]), "+f"(acc[mi][ni][3])
                    : "r"(af[mi][0]), "r"(af[mi][1]), "r"(af[mi][2]), "r"(af[mi][3]),
                      "r"(bf[ni][0]), "r"(bf[ni][1]));
            }
        if (more) {
            int nb = buf ^ 1;
            As[nb][lK + 0][lRow] = to_tf32(pa.x); As[nb][lK + 1][lRow] = to_tf32(pa.y);
            As[nb][lK + 2][lRow] = to_tf32(pa.z); As[nb][lK + 3][lRow] = to_tf32(pa.w);
            Bs[nb][lK + 0][lRow] = to_tf32(pb.x); Bs[nb][lK + 1][lRow] = to_tf32(pb.y);
            Bs[nb][lK + 2][lRow] = to_tf32(pb.z); Bs[nb][lK + 3][lRow] = to_tf32(pb.w);
        }
        __syncthreads();
        buf ^= 1;
    }

    #pragma unroll
    for (int mi = 0; mi < 4; mi++) {
        int r0 = m0 + wm + mi * 16 + g;
        #pragma unroll
        for (int ni = 0; ni < 4; ni++) {
            int cc = n0 + wn + ni * 8 + 2 * tig;
            float2 bb = make_float2(0.f, 0.f);
            if (bias) bb = *(const float2*)(bias + cc);
            float2 v0 = make_float2(acc[mi][ni][0] + bb.x, acc[mi][ni][1] + bb.y);
            float2 v1 = make_float2(acc[mi][ni][2] + bb.x, acc[mi][ni][3] + bb.y);
            *(float2*)(C + (size_t)r0 * N + cc)       = v0;
            *(float2*)(C + (size_t)(r0 + 8) * N + cc) = v1;
        }
    }
}

// generic TF32 GEMM (used for out_proj)
__global__ __launch_bounds__(256) void gemm_tf32(
    const float* __restrict__ Abase,
    const float* __restrict__ B0, const float* __restrict__ B1,
    const float* __restrict__ bias,
    float* __restrict__ Cbase,
    int N, int K, size_t dsA, size_t dsC)
{
    const int dir = blockIdx.z;
    gemm_tf32_body(Abase + (size_t)dir * dsA, dir ? B1 : B0, bias,
                   Cbase + (size_t)dir * dsC,
                   blockIdx.y * 128, blockIdx.x * 128, N, K);
}

// merged: z<2 -> in_proj (N=512,K=128), z==2 -> pointwise conv (N=128,K=128)
__global__ __launch_bounds__(256) void gemm_tf32_multi(
    const float* __restrict__ xnorm,
    const float* __restrict__ inw0, const float* __restrict__ inw1,
    float* __restrict__ xz,
    const float* __restrict__ gbuf, const float* __restrict__ pww,
    const float* __restrict__ pwb, float* __restrict__ lfb)
{
    const int z = blockIdx.z;
    if (z < 2) {
        gemm_tf32_body(xnorm + (size_t)z * MR * CDIM, z ? inw1 : inw0, nullptr,
                       xz + (size_t)z * MR * 512,
                       blockIdx.y * 128, blockIdx.x * 128, 512, 128);
    } else {
        if (blockIdx.x != 0) return;
        gemm_tf32_body(gbuf, pww, pwb, lfb, blockIdx.y * 128, 0, 128, 128);
    }
}

// ========== x_proj GEMM (BM=32, N=40, K=256) + fused dt softplus ==========
__global__ __launch_bounds__(256) void xproj_dt(
    const float* __restrict__ xsg,
    const float* __restrict__ W0, const float* __restrict__ W1,
    const float* __restrict__ dtw0, const float* __restrict__ dtw1,
    const float* __restrict__ dtb0, const float* __restrict__ dtb1,
    float* __restrict__ dblg, float* __restrict__ dtg)
{
    const int dir = blockIdx.z;
    const float* A   = xsg + (size_t)dir * MR * DI;
    const float* Bw  = dir ? W1 : W0;
    const float* dtw = dir ? dtw1 : dtw0;
    const float* dtb = dir ? dtb1 : dtb0;
    float* dbl = dblg + (size_t)dir * MR * 40;
    float* dto = dtg  + (size_t)dir * MR * DI;
    const int m0 = blockIdx.y * 32;
    const int K = 256;

    __shared__ float As[2][16][36];
    __shared__ float Bs[2][16][68];
    __shared__ float sdt[32][9];

    const int t = threadIdx.x;
    const int tx = t & 15, ty = t >> 4;
    const int aRow = t >> 2;           // 0..63
    const int aK   = (t & 3) * 4;
    const bool aAct = aRow < 32;
    const bool bValid = aRow < 40;

    const float* Aptr = A + (size_t)(m0 + (aAct ? aRow : 0)) * K + aK;
    const float* Bptr = Bw + (size_t)(bValid ? aRow : 0) * K + aK;

    float4 pa = aAct ? *(const float4*)(Aptr) : make_float4(0, 0, 0, 0);
    float4 pb = bValid ? *(const float4*)(Bptr) : make_float4(0, 0, 0, 0);

    float acc[2][4];
    #pragma unroll
    for (int i = 0; i < 2; i++)
        #pragma unroll
        for (int j = 0; j < 4; j++) acc[i][j] = 0.f;

    if (aAct) {
        As[0][aK + 0][aRow] = pa.x; As[0][aK + 1][aRow] = pa.y;
        As[0][aK + 2][aRow] = pa.z; As[0][aK + 3][aRow] = pa.w;
    }
    Bs[0][aK + 0][aRow] = pb.x; Bs[0][aK + 1][aRow] = pb.y;
    Bs[0][aK + 2][aRow] = pb.z; Bs[0][aK + 3][aRow] = pb.w;
    __syncthreads();

    int buf = 0;
    for (int kt = 0; kt < 16; kt++) {
        bool more = (kt + 1 < 16);
        if (more) {
            if (aAct)   pa = *(const float4*)(Aptr + (kt + 1) * 16);
            if (bValid) pb = *(const float4*)(Bptr + (kt + 1) * 16);
        }
        #pragma unroll
        for (int k = 0; k < 16; k++) {
            float2 a = *(const float2*)&As[buf][k][ty * 2];
            float4 b = *(const float4*)&Bs[buf][k][tx * 4];
            float av[2] = {a.x, a.y};
            float bv[4] = {b.x, b.y, b.z, b.w};
            #pragma unroll
            for (int i = 0; i < 2; i++)
                #pragma unroll
                for (int j = 0; j < 4; j++) acc[i][j] = fmaf(av[i], bv[j], acc[i][j]);
        }
        if (more) {
            int nb = buf ^ 1;
            if (aAct) {
                As[nb][aK + 0][aRow] = pa.x; As[nb][aK + 1][aRow] = pa.y;
                As[nb][aK + 2][aRow] = pa.z; As[nb][aK + 3][aRow] = pa.w;
            }
            Bs[nb][aK + 0][aRow] = pb.x; Bs[nb][aK + 1][aRow] = pb.y;
            Bs[nb][aK + 2][aRow] = pb.z; Bs[nb][aK + 3][aRow] = pb.w;
        }
        __syncthreads();
        buf ^= 1;
    }

    if (tx < 10) {
        #pragma unroll
        for (int i = 0; i < 2; i++) {
            float4 v = make_float4(acc[i][0], acc[i][1], acc[i][2], acc[i][3]);
            *(float4*)(dbl + (size_t)(m0 + ty * 2 + i) * 40 + tx * 4) = v;
        }
    }
    if (tx < 2) {
        #pragma unroll
        for (int i = 0; i < 2; i++)
            #pragma unroll
            for (int j = 0; j < 4; j++)
                sdt[ty * 2 + i][tx * 4 + j] = acc[i][j];
    }
    __syncthreads();

    int d = t;
    float w[8];
    #pragma unroll
    for (int r = 0; r < 8; r++) w[r] = dtw[d * 8 + r];
    float db = dtb[d];
    for (int row = 0; row < 32; row++) {
        float s = db;
        #pragma unroll
        for (int r = 0; r < 8; r++) s = fmaf(sdt[row][r], w[r], s);
        float sp = (s > 20.f) ? s : __logf(1.f + __expf(s));
        dto[(size_t)(m0 + row) * DI + d] = sp;
    }
}

// ========== causal conv1d k=4 + silu, rolling window: 8 positions/thread ====
__global__ __launch_bounds__(256) void conv_silu(
    const float* __restrict__ xzg,
    const float* __restrict__ cw0, const float* __restrict__ cw1,
    const float* __restrict__ cb0, const float* __restrict__ cb1,
    float* __restrict__ xsg)
{
    const int dir = blockIdx.y;
    const float* xz = xzg + (size_t)dir * MR * 512;
    const float* cw = dir ? cw1 : cw0;
    const float* cb = dir ? cb1 : cb0;
    float* xs = xsg + (size_t)dir * MR * DI;
    int idx = blockIdx.x * 256 + threadIdx.x;
    if (idx >= (MR / 8) * 64) return;
    int d4 = idx & 63;
    int mt = idx >> 6;
    int m0 = mt * 8;
    int l0 = m0 % LSEQ;
    int d  = d4 * 4;
    float4 bias = *(const float4*)(cb + d);
    float4 wk[4];
    #pragma unroll
    for (int k = 0; k < 4; k++) {
        wk[k].x = cw[(d + 0) * 4 + k];
        wk[k].y = cw[(d + 1) * 4 + k];
        wk[k].z = cw[(d + 2) * 4 + k];
        wk[k].w = cw[(d + 3) * 4 + k];
    }
    const float4 zero = make_float4(0.f, 0.f, 0.f, 0.f);
    float4 r0 = (l0 >= 3) ? *(const float4*)(xz + (size_t)(m0 - 3) * 512 + d) : zero;
    float4 r1 = (l0 >= 2) ? *(const float4*)(xz + (size_t)(m0 - 2) * 512 + d) : zero;
    float4 r2 = (l0 >= 1) ? *(const float4*)(xz + (size_t)(m0 - 1) * 512 + d) : zero;
    #pragma unroll
    for (int tt = 0; tt < 8; tt++) {
        float4 cur = *(const float4*)(xz + (size_t)(m0 + tt) * 512 + d);
        float4 a = bias;
        a.x = fmaf(r0.x, wk[0].x, a.x); a.y = fmaf(r0.y, wk[0].y, a.y);
        a.z = fmaf(r0.z, wk[0].z, a.z); a.w = fmaf(r0.w, wk[0].w, a.w);
        a.x = fmaf(r1.x, wk[1].x, a.x); a.y = fmaf(r1.y, wk[1].y, a.y);
        a.z = fmaf(r1.z, wk[1].z, a.z); a.w = fmaf(r1.w, wk[1].w, a.w);
        a.x = fmaf(r2.x, wk[2].x, a.x); a.y = fmaf(r2.y, wk[2].y, a.y);
        a.z = fmaf(r2.z, wk[2].z, a.z); a.w = fmaf(r2.w, wk[2].w, a.w);
        a.x = fmaf(cur.x, wk[3].x, a.x); a.y = fmaf(cur.y, wk[3].y, a.y);
        a.z = fmaf(cur.z, wk[3].z, a.z); a.w = fmaf(cur.w, wk[3].w, a.w);
        float4 o;
        o.x = a.x / (1.f + __expf(-a.x));
        o.y = a.y / (1.f + __expf(-a.y));
        o.z = a.z / (1.f + __expf(-a.z));
        o.w = a.w / (1.f + __expf(-a.w));
        *(float4*)(xs + (size_t)(m0 + tt) * DI + d) = o;
        r0 = r1; r1 = r2; r2 = cur;
    }
}

// ========== scan pass A ==========
__global__ __launch_bounds__(256) void scanA(
    const float* __restrict__ dtg, const float* __restrict__ xsg,
    const float* __restrict__ dblg,
    const float* __restrict__ Al0, const float* __restrict__ Al1,
    float* __restrict__ Pcg, float* __restrict__ Hcg)
{
    int d = threadIdx.x, chunk = blockIdx.x, b = blockIdx.y, dir = blockIdx.z;
    const float* dt  = dtg + (size_t)dir * MR * DI;
    const float* xs  = xsg + (size_t)dir * MR * DI;
    const float* dbl = dblg + (size_t)dir * MR * 40;
    const float* Al  = dir ? Al1 : Al0;
    float* Pc = Pcg + (size_t)dir * NC * BATCH * DI * DS;
    float* Hc = Hcg + (size_t)dir * NC * BATCH * DI * DS;
    __shared__ float sB[CL][16];
    int base = b * LSEQ + chunk * CL;
    for (int i = d; i < CL * 16; i += 256) {
        int l = i >> 4, n = i & 15;
        sB[l][n] = dbl[(size_t)(base + l) * 40 + 8 + n];
    }
    float a[16]; bool fast = true;
    #pragma unroll
    for (int n = 0; n < 16; n++) {
        a[n] = -__expf(Al[d * 16 + n]);
        fast = fast && (fabsf(a[n] + (float)(n + 1)) <= 1e-4f * (n + 1));
    }
    __syncthreads();
    float h[16], pp[16];
    #pragma unroll
    for (int n = 0; n < 16; n++) { h[n] = 0.f; pp[n] = 1.f; }
    if (fast) {
        for (int l = 0; l < CL; l++) {
            float dtv = dt[(size_t)(base + l) * DI + d];
            float xsv = xs[(size_t)(base + l) * DI + d];
            float du = dtv * xsv;
            float e1 = __expf(-dtv);
            float e[16]; e[0] = e1;
            #pragma unroll
            for (int n = 1; n < 16; n++) e[n] = e[n - 1] * e1;
            #pragma unroll
            for (int n = 0; n < 16; n++) {
                pp[n] *= e[n];
                h[n] = fmaf(e[n], h[n], du * sB[l][n]);
            }
        }
    } else {
        for (int l = 0; l < CL; l++) {
            float dtv = dt[(size_t)(base + l) * DI + d];
            float xsv = xs[(size_t)(base + l) * DI + d];
            float du = dtv * xsv;
            #pragma unroll
            for (int n = 0; n < 16; n++) {
                float e = __expf(dtv * a[n]);
                pp[n] *= e;
                h[n] = fmaf(e, h[n], du * sB[l][n]);
            }
        }
    }
    size_t o = (((size_t)chunk * BATCH + b) * DI + d) * DS;
    #pragma unroll
    for (int n = 0; n < 16; n++) { Pc[o + n] = pp[n]; Hc[o + n] = h[n]; }
}

// ========== scan pass B ==========
__global__ void scanB(const float* __restrict__ Pcg, const float* __restrict__ Hcg,
                      float* __restrict__ Hig)
{
    int dir = blockIdx.y;
    const float* Pc = Pcg + (size_t)dir * NC * BATCH * DI * DS;
    const float* Hc = Hcg + (size_t)dir * NC * BATCH * DI * DS;
    float* Hi = Hig + (size_t)dir * NC * BATCH * DI * DS;
    int idx = blockIdx.x * 256 + threadIdx.x;
    if (idx >= BATCH * DI * DS) return;
    float h = 0.f;
    for (int c = 0; c < NC; c++) {
        size_t o = (size_t)c * (BATCH * DI * DS) + idx;
        Hi[o] = h;
        h = fmaf(Pc[o], h, Hc[o]);
    }
}

// ========== scan pass C + gate fused ==========
__global__ __launch_bounds__(256) void scanC(
    const float* __restrict__ dtg, const float* __restrict__ xsg,
    const float* __restrict__ dblg, const float* __restrict__ xzg,
    const float* __restrict__ Al0, const float* __restrict__ Al1,
    const float* __restrict__ D0, const float* __restrict__ D1,
    const float* __restrict__ Hig, float* __restrict__ ysg)
{
    int d = threadIdx.x, chunk = blockIdx.x, b = blockIdx.y, dir = blockIdx.z;
    const float* dt  = dtg + (size_t)dir * MR * DI;
    const float* xs  = xsg + (size_t)dir * MR * DI;
    const float* dbl = dblg + (size_t)dir * MR * 40;
    const float* xz  = xzg + (size_t)dir * MR * 512;
    const float* Al  = dir ? Al1 : Al0;
    const float* Dp  = dir ? D1 : D0;
    const float* Hi  = Hig + (size_t)dir * NC * BATCH * DI * DS;
    float* ys = ysg + (size_t)dir * MR * DI;
    __shared__ float sBC[CL][32];
    int base = b * LSEQ + chunk * CL;
    for (int i = d; i < CL * 32; i += 256) {
        int l = i >> 5, j = i & 31;
        sBC[l][j] = dbl[(size_t)(base + l) * 40 + 8 + j];
    }
    float a[16]; bool fast = true;
    #pragma unroll
    for (int n = 0; n < 16; n++) {
        a[n] = -__expf(Al[d * 16 + n]);
        fast = fast && (fabsf(a[n] + (float)(n + 1)) <= 1e-4f * (n + 1));
    }
    float Dd = Dp[d];
    float h[16];
    size_t o = (((size_t)chunk * BATCH + b) * DI + d) * DS;
    #pragma unroll
    for (int n = 0; n < 16; n++) h[n] = Hi[o + n];
    __syncthreads();
    if (fast) {
        for (int l = 0; l < CL; l++) {
            float dtv = dt[(size_t)(base + l) * DI + d];
            float xsv = xs[(size_t)(base + l) * DI + d];
            float zv  = xz[(size_t)(base + l) * 512 + 256 + d];
            float du = dtv * xsv;
            float e1 = __expf(-dtv);
            float e[16]; e[0] = e1;
            #pragma unroll
            for (int n = 1; n < 16; n++) e[n] = e[n - 1] * e1;
            float y = 0.f;
            #pragma unroll
            for (int n = 0; n < 16; n++) {
                h[n] = fmaf(e[n], h[n], du * sBC[l][n]);
                y = fmaf(h[n], sBC[l][16 + n], y);
            }
            float sz = zv / (1.f + __expf(-zv));
            ys[(size_t)(base + l) * DI + d] = (y + xsv * Dd) * sz;
        }
    } else {
        for (int l = 0; l < CL; l++) {
            float dtv = dt[(size_t)(base + l) * DI + d];
            float xsv = xs[(size_t)(base + l) * DI + d];
            float zv  = xz[(size_t)(base + l) * 512 + 256 + d];
            float du = dtv * xsv;
            float y = 0.f;
            #pragma unroll
            for (int n = 0; n < 16; n++) {
                float e = __expf(dtv * a[n]);
                h[n] = fmaf(e, h[n], du * sBC[l][n]);
                y = fmaf(h[n], sBC[l][16 + n], y);
            }
            float sz = zv / (1.f + __expf(-zv));
            ys[(size_t)(base + l) * DI + d] = (y + xsv * Dd) * sz;
        }
    }
}

// ========== fuse oh+ov+lf, partial sums ==========
__global__ void fuse_kernel(const float* __restrict__ oh, const float* __restrict__ ov,
                            const float* __restrict__ lf, float* __restrict__ fused,
                            float* __restrict__ psum)
{
    int c = threadIdx.x;
    int pc = blockIdx.x;
    int b  = blockIdx.y;
    float s = 0.f;
    for (int i = 0; i < 32; i++) {
        int p = pc * 32 + i;
        int pv = (p % WWD) * HH + p / WWD;
        float f = oh[((size_t)(b * LSEQ + p)) * 128 + c]
                + ov[((size_t)(b * LSEQ + pv)) * 128 + c]
                + lf[((size_t)(b * PPOS + p)) * 128 + c];
        fused[((size_t)(b * PPOS + p)) * 128 + c] = f;
        s += f;
    }
    psum[((size_t)b * 98 + pc) * 128 + c] = s;
}

// ========== final: channel attention (recomputed per block) + residual ==========
__global__ __launch_bounds__(256) void final_attn(
    const float* __restrict__ psum,
    const float* __restrict__ fc1, const float* __restrict__ fc2,
    const float* __restrict__ fused, const float* __restrict__ x,
    float* __restrict__ out)
{
    __shared__ float spart[2][128];
    __shared__ float sm[128];
    __shared__ float t1[32];
    __shared__ float satn[128];
    __shared__ float sf[128][33];
    int t = threadIdx.x;
    int p0 = blockIdx.x * 32;
    int b  = blockIdx.y;
    {
        int c = t & 127, half = t >> 7;
        float s = 0.f;
        for (int pc = half * 49; pc < half * 49 + 49; pc++)
            s += psum[((size_t)b * 98 + pc) * 128 + c];
        spart[half][c] = s;
    }
    __syncthreads();
    if (t < 128) sm[t] = (spart[0][t] + spart[1][t]) * (1.f / (float)PPOS);
    __syncthreads();
    if (t < 32) {
        float acc = 0.f;
        #pragma unroll 4
        for (int c = 0; c < 128; c++) acc = fmaf(sm[c], fc1[t * 128 + c], acc);
        t1[t] = fmaxf(acc, 0.f);
    }
    __syncthreads();
    if (t < 128) {
        float acc = 0.f;
        #pragma unroll
        for (int i = 0; i < 32; i++) acc = fmaf(t1[i], fc2[t * 32 + i], acc);
        satn[t] = 1.f / (1.f + __expf(-acc));
    }
    {
        int c = t & 127, ph = t >> 7;
        #pragma unroll
        for (int pass = 0; pass < 16; pass++) {
            int pl = pass * 2 + ph;
            sf[c][pl] = fused[((size_t)(b * PPOS + p0 + pl)) * 128 + c];
        }
    }
    __syncthreads();
    int pl = t & 31, c8 = t >> 5;
    #pragma unroll
    for (int pass = 0; pass < 16; pass++) {
        int c = pass * 8 + c8;
        size_t gi = ((size_t)(b * 128 + c)) * PPOS + p0 + pl;
        out[gi] = sf[c][pl] * satn[c] + x[gi];
    }
}

// ============================================================================
extern "C" void kernel_launch(void* const* d_in, const int* in_sizes, int n_in,
                              void* d_out, int out_size)
{
    const float* x       = (const float*)d_in[0];
    const float* norm_hw = (const float*)d_in[1];
    const float* norm_hb = (const float*)d_in[2];
    const float* norm_vw = (const float*)d_in[3];
    const float* norm_vb = (const float*)d_in[4];
    const float* dw_w    = (const float*)d_in[5];
    const float* dw_b    = (const float*)d_in[6];
    const float* pw_w    = (const float*)d_in[7];
    const float* pw_b    = (const float*)d_in[8];
    const float* in_w0    = (const float*)d_in[9];
    const float* conv_w0  = (const float*)d_in[10];
    const float* conv_b0  = (const float*)d_in[11];
    const float* xproj_w0 = (const float*)d_in[12];
    const float* dt_w0    = (const float*)d_in[13];
    const float* dt_b0    = (const float*)d_in[14];
    const float* A_log0   = (const float*)d_in[15];
    const float* D0       = (const float*)d_in[16];
    const float* out_w0   = (const float*)d_in[17];
    const float* in_w1    = (const float*)d_in[18];
    const float* conv_w1  = (const float*)d_in[19];
    const float* conv_b1  = (const float*)d_in[20];
    const float* xproj_w1 = (const float*)d_in[21];
    const float* dt_w1    = (const float*)d_in[22];
    const float* dt_b1    = (const float*)d_in[23];
    const float* A_log1   = (const float*)d_in[24];
    const float* D1       = (const float*)d_in[25];
    const float* out_w1   = (const float*)d_in[26];
    const float* fc1     = (const float*)d_in[27];
    const float* fc2     = (const float*)d_in[28];

    void* p;
    cudaGetSymbolAddress(&p, g_xnorm); float* xnorm = (float*)p;
    cudaGetSymbolAddress(&p, g_xz);    float* xz    = (float*)p;
    cudaGetSymbolAddress(&p, g_xs);    float* xs    = (float*)p;
    cudaGetSymbolAddress(&p, g_dbl);   float* dbl   = (float*)p;
    cudaGetSymbolAddress(&p, g_dt);    float* dt    = (float*)p;
    cudaGetSymbolAddress(&p, g_ys);    float* ys    = (float*)p;
    cudaGetSymbolAddress(&p, g_o);     float* ob    = (float*)p;
    cudaGetSymbolAddress(&p, g_g);     float* gbuf  = (float*)p;
    cudaGetSymbolAddress(&p, g_lf);    float* lfb   = (float*)p;
    cudaGetSymbolAddress(&p, g_fused); float* fused = (float*)p;
    cudaGetSymbolAddress(&p, g_Pc);    float* Pc    = (float*)p;
    cudaGetSymbolAddress(&p, g_Hc);    float* Hc    = (float*)p;
    cudaGetSymbolAddress(&p, g_Hi);    float* Hi    = (float*)p;
    cudaGetSymbolAddress(&p, g_psum);  float* psum  = (float*)p;

    // prep: layernorm (both layouts) + local-feature dwconv+gelu
    prep_kernel<<<dim3(98, 2), 256>>>(x, norm_hw, norm_hb, norm_vw, norm_vb,
                                      dw_w, dw_b,
                                      xnorm, xnorm + (size_t)MR * CDIM, gbuf);
    // in_proj (z<2) + pointwise conv (z=2), all TF32, one launch
    gemm_tf32_multi<<<dim3(4, 49, 3), 256>>>(xnorm, in_w0, in_w1, xz,
                                             gbuf, pw_w, pw_b, lfb);
    // conv + silu (rolling window, 8 pos/thread)
    conv_silu<<<dim3((MR / 8) * 64 / 256, 2), 256>>>(xz, conv_w0, conv_w1,
                                                     conv_b0, conv_b1, xs);
    // x_proj + dt fused (BM=32, 392 blocks)
    xproj_dt<<<dim3(1, 196, 2), 256>>>(xs, xproj_w0, xproj_w1, dt_w0, dt_w1,
                                       dt_b0, dt_b1, dbl, dt);
    // selective scan
    scanA<<<dim3(NC, BATCH, 2), 256>>>(dt, xs, dbl, A_log0, A_log1, Pc, Hc);
    scanB<<<dim3(32, 2), 256>>>(Pc, Hc, Hi);
    scanC<<<dim3(NC, BATCH, 2), 256>>>(dt, xs, dbl, xz, A_log0, A_log1, D0, D1, Hi, ys);
    // out_proj: TF32 tensor cores, 128x128 tiles, 98 blocks
    gemm_tf32<<<dim3(1, 49, 2), 256>>>(ys, out_w0, out_w1, nullptr, ob,
                                       128, 256, (size_t)MR * DI, (size_t)MR * CDIM);
    // fuse + attention + residual
    fuse_kernel<<<dim3(98, 2), 128>>>(ob, ob + (size_t)MR * CDIM, lfb, fused, psum);
    final_attn<<<dim3(98, 2), 256>>>(psum, fc1, fc2, fused, x, (float*)d_out);
}

// round 14
// speedup vs baseline: 1.0083x; 1.0083x over previous
#include <cuda_runtime.h>
#include <cuda_bf16.h>
#include <cstddef>
#include <cstdint>

#define BATCH 2
#define CDIM  128
#define HH    56
#define WWD   56
#define PPOS  3136
#define LSEQ  3136
#define MR    6272
#define DI    256
#define DS    16
#define NC    49
#define CL    64

// ---------------- scratch ----------------
__device__ __align__(16) float g_xnorm[2][MR * CDIM];
__device__ __align__(16) float g_xz   [2][MR * 512];
__device__ __align__(16) float g_xs   [2][MR * DI];
__device__ __align__(16) float g_dbl  [2][MR * 40];
__device__ __align__(16) float g_ys   [2][MR * DI];
__device__ __align__(16) float g_o    [2][MR * CDIM];
__device__ __align__(16) float g_g    [MR * CDIM];
__device__ __align__(16) float g_lf   [MR * CDIM];
__device__ __align__(16) float g_fused[MR * CDIM];
__device__ __align__(16) float g_Pc [2][NC * BATCH * DI * DS];
__device__ __align__(16) float g_Hc [2][NC * BATCH * DI * DS];
__device__ __align__(16) float g_Hi [2][NC * BATCH * DI * DS];
__device__ __align__(16) float g_psum[BATCH * 98 * CDIM];

__device__ __forceinline__ float to_tf32(float x) {
    unsigned int u;
    asm("cvt.rna.tf32.f32 %0, %1;" : "=r"(u) : "f"(x));
    return __uint_as_float(u);
}

// ========== prep: LayerNorm (both layouts) + depthwise 3x3 + GELU ==========
__global__ __launch_bounds__(256) void prep_kernel(
    const float* __restrict__ x,
    const float* __restrict__ hw, const float* __restrict__ hb,
    const float* __restrict__ vw, const float* __restrict__ vb,
    const float* __restrict__ dww, const float* __restrict__ dwb,
    float* __restrict__ xh, float* __restrict__ xv, float* __restrict__ g)
{
    __shared__ float sx[128][33];
    __shared__ float part[8][33];
    __shared__ float partq[8][33];
    __shared__ float mu[32], rs[32];
    __shared__ float sg[128][33];
    int t = threadIdx.x;
    int p0 = blockIdx.x * 32;
    int b  = blockIdx.y;
    int pl = t & 31, c8 = t >> 5;
    float s = 0.f, sq = 0.f;
    #pragma unroll
    for (int pass = 0; pass < 16; pass++) {
        int c = pass * 8 + c8;
        float v = x[((size_t)(b * 128 + c)) * PPOS + p0 + pl];
        sx[c][pl] = v;
        s += v; sq += v * v;
    }
    part[c8][pl] = s; partq[c8][pl] = sq;
    __syncthreads();
    if (t < 32) {
        float S = 0.f, Q = 0.f;
        #pragma unroll
        for (int r = 0; r < 8; r++) { S += part[r][t]; Q += partq[r][t]; }
        float mean = S * (1.f / 128.f);
        float var  = Q * (1.f / 128.f) - mean * mean;
        mu[t] = mean;
        rs[t] = rsqrtf(var + 1e-5f);
    }
    __syncthreads();
    {
        int c = t & 127, ph = t >> 7;
        float whh = hw[c], bhh = hb[c], wvv = vw[c], bvv = vb[c];
        #pragma unroll
        for (int pass = 0; pass < 16; pass++) {
            int pl2 = pass * 2 + ph;
            int p = p0 + pl2;
            float xc = (sx[c][pl2] - mu[pl2]) * rs[pl2];
            int h = p / WWD, w = p % WWD;
            xh[((size_t)b * LSEQ + p) * 128 + c]            = xc * whh + bhh;
            xv[((size_t)b * LSEQ + (w * HH + h)) * 128 + c] = xc * wvv + bvv;
        }
    }
    {
        int p = p0 + pl;
        int h = p / WWD, w = p % WWD;
        #pragma unroll
        for (int pass = 0; pass < 16; pass++) {
            int c = pass * 8 + c8;
            const float* xb = x + ((size_t)(b * 128 + c)) * PPOS;
            float acc = dwb[c];
            #pragma unroll
            for (int kh = 0; kh < 3; kh++) {
                int hh = h + kh - 1;
                if (hh < 0 || hh >= HH) continue;
                #pragma unroll
                for (int kw = 0; kw < 3; kw++) {
                    int ww = w + kw - 1;
                    if (ww < 0 || ww >= WWD) continue;
                    acc = fmaf(xb[hh * WWD + ww], dww[c * 9 + kh * 3 + kw], acc);
                }
            }
            sg[c][pl] = 0.5f * acc * (1.f + erff(acc * 0.70710678118654752f));
        }
    }
    __syncthreads();
    {
        int c = t & 127, ph = t >> 7;
        #pragma unroll
        for (int pass = 0; pass < 16; pass++) {
            int pl2 = pass * 2 + ph;
            g[((size_t)(b * PPOS + p0 + pl2)) * 128 + c] = sg[c][pl2];
        }
    }
}

// ========== TF32 GEMM core (device func): 128x128 block, 8 warps ==========
__device__ __forceinline__ void gemm_tf32_body(
    const float* __restrict__ A, const float* __restrict__ Bw,
    const float* __restrict__ bias, float* __restrict__ C,
    int m0, int n0, int N, int K)
{
    __shared__ float As[2][8][136];
    __shared__ float Bs[2][8][136];

    const int t    = threadIdx.x;
    const int lane = t & 31;
    const int wid  = t >> 5;
    const int g    = lane >> 2;
    const int tig  = lane & 3;
    const int wm   = (wid & 1) * 64;
    const int wn   = (wid >> 1) * 32;

    const int lRow = t >> 1;
    const int lK   = (t & 1) * 4;

    const float* Aptr = A + (size_t)(m0 + lRow) * K + lK;
    const float* Bptr = Bw + (size_t)(n0 + lRow) * K + lK;

    float4 pa = *(const float4*)Aptr;
    float4 pb = *(const float4*)Bptr;

    float acc[4][4][4];
    #pragma unroll
    for (int mi = 0; mi < 4; mi++)
        #pragma unroll
        for (int ni = 0; ni < 4; ni++)
            #pragma unroll
            for (int r = 0; r < 4; r++) acc[mi][ni][r] = 0.f;

    As[0][lK + 0][lRow] = to_tf32(pa.x); As[0][lK + 1][lRow] = to_tf32(pa.y);
    As[0][lK + 2][lRow] = to_tf32(pa.z); As[0][lK + 3][lRow] = to_tf32(pa.w);
    Bs[0][lK + 0][lRow] = to_tf32(pb.x); Bs[0][lK + 1][lRow] = to_tf32(pb.y);
    Bs[0][lK + 2][lRow] = to_tf32(pb.z); Bs[0][lK + 3][lRow] = to_tf32(pb.w);
    __syncthreads();

    const int nt = K >> 3;
    int buf = 0;
    for (int kt = 0; kt < nt; kt++) {
        bool more = (kt + 1 < nt);
        if (more) {
            pa = *(const float4*)(Aptr + (kt + 1) * 8);
            pb = *(const float4*)(Bptr + (kt + 1) * 8);
        }
        unsigned int af[4][4], bf[4][2];
        #pragma unroll
        for (int mi = 0; mi < 4; mi++) {
            int rm = wm + mi * 16 + g;
            af[mi][0] = __float_as_uint(As[buf][tig][rm]);
            af[mi][1] = __float_as_uint(As[buf][tig][rm + 8]);
            af[mi][2] = __float_as_uint(As[buf][tig + 4][rm]);
            af[mi][3] = __float_as_uint(As[buf][tig + 4][rm + 8]);
        }
        #pragma unroll
        for (int ni = 0; ni < 4; ni++) {
            int cn = wn + ni * 8 + g;
            bf[ni][0] = __float_as_uint(Bs[buf][tig][cn]);
            bf[ni][1] = __float_as_uint(Bs[buf][tig + 4][cn]);
        }
        #pragma unroll
        for (int mi = 0; mi < 4; mi++)
            #pragma unroll
            for (int ni = 0; ni < 4; ni++) {
                asm volatile(
                    "mma.sync.aligned.m16n8k8.row.col.f32.tf32.tf32.f32 "
                    "{%0,%1,%2,%3}, {%4,%5,%6,%7}, {%8,%9}, {%0,%1,%2,%3};\n"
                    : "+f"(acc[mi][ni][0]), "+f"(acc[mi][ni][1]),
                      "+f"(acc[mi][ni][2]), "+f"(acc[mi][ni][3])
                    : "r"(af[mi][0]), "r"(af[mi][1]), "r"(af[mi][2]), "r"(af[mi][3]),
                      "r"(bf[ni][0]), "r"(bf[ni][1]));
            }
        if (more) {
            int nb = buf ^ 1;
            As[nb][lK + 0][lRow] = to_tf32(pa.x); As[nb][lK + 1][lRow] = to_tf32(pa.y);
            As[nb][lK + 2][lRow] = to_tf32(pa.z); As[nb][lK + 3][lRow] = to_tf32(pa.w);
            Bs[nb][lK + 0][lRow] = to_tf32(pb.x); Bs[nb][lK + 1][lRow] = to_tf32(pb.y);
            Bs[nb][lK + 2][lRow] = to_tf32(pb.z); Bs[nb][lK + 3][lRow] = to_tf32(pb.w);
        }
        __syncthreads();
        buf ^= 1;
    }

    #pragma unroll
    for (int mi = 0; mi < 4; mi++) {
        int r0 = m0 + wm + mi * 16 + g;
        #pragma unroll
        for (int ni = 0; ni < 4; ni++) {
            int cc = n0 + wn + ni * 8 + 2 * tig;
            float2 bb = make_float2(0.f, 0.f);
            if (bias) bb = *(const float2*)(bias + cc);
            float2 v0 = make_float2(acc[mi][ni][0] + bb.x, acc[mi][ni][1] + bb.y);
            float2 v1 = make_float2(acc[mi][ni][2] + bb.x, acc[mi][ni][3] + bb.y);
            *(float2*)(C + (size_t)r0 * N + cc)       = v0;
            *(float2*)(C + (size_t)(r0 + 8) * N + cc) = v1;
        }
    }
}

// generic TF32 GEMM (used for out_proj)
__global__ __launch_bounds__(256) void gemm_tf32(
    const float* __restrict__ Abase,
    const float* __restrict__ B0, const float* __restrict__ B1,
    const float* __restrict__ bias,
    float* __restrict__ Cbase,
    int N, int K, size_t dsA, size_t dsC)
{
    const int dir = blockIdx.z;
    gemm_tf32_body(Abase + (size_t)dir * dsA, dir ? B1 : B0, bias,
                   Cbase + (size_t)dir * dsC,
                   blockIdx.y * 128, blockIdx.x * 128, N, K);
}

// merged: z<2 -> in_proj (N=512,K=128), z==2 -> pointwise conv (N=128,K=128)
__global__ __launch_bounds__(256) void gemm_tf32_multi(
    const float* __restrict__ xnorm,
    const float* __restrict__ inw0, const float* __restrict__ inw1,
    float* __restrict__ xz,
    const float* __restrict__ gbuf, const float* __restrict__ pww,
    const float* __restrict__ pwb, float* __restrict__ lfb)
{
    const int z = blockIdx.z;
    if (z < 2) {
        gemm_tf32_body(xnorm + (size_t)z * MR * CDIM, z ? inw1 : inw0, nullptr,
                       xz + (size_t)z * MR * 512,
                       blockIdx.y * 128, blockIdx.x * 128, 512, 128);
    } else {
        if (blockIdx.x != 0) return;
        gemm_tf32_body(gbuf, pww, pwb, lfb, blockIdx.y * 128, 0, 128, 128);
    }
}

// ========== x_proj GEMM via TF32: M-tile=128, N=40 (B rows guarded) =========
// Full ni range computed (dead cols are free on tensor pipe); writes guarded.
__global__ __launch_bounds__(256) void xproj_tf32(
    const float* __restrict__ xsg,
    const float* __restrict__ W0, const float* __restrict__ W1,
    float* __restrict__ dblg)
{
    const int dir = blockIdx.z;
    const float* A  = xsg + (size_t)dir * MR * DI;
    const float* Bw = dir ? W1 : W0;
    float* C = dblg + (size_t)dir * MR * 40;
    const int m0 = blockIdx.y * 128;
    const int K = 256;

    __shared__ float As[2][8][136];
    __shared__ float Bs[2][8][136];

    const int t    = threadIdx.x;
    const int lane = t & 31;
    const int wid  = t >> 5;
    const int g    = lane >> 2;
    const int tig  = lane & 3;
    const int wm   = (wid & 1) * 64;
    const int wn   = (wid >> 1) * 32;

    const int lRow = t >> 1;
    const int lK   = (t & 1) * 4;
    const bool bAct = lRow < 40;

    const float* Aptr = A + (size_t)(m0 + lRow) * K + lK;
    const float* Bptr = Bw + (size_t)(bAct ? lRow : 0) * K + lK;

    float4 pa = *(const float4*)Aptr;
    float4 pb = bAct ? *(const float4*)Bptr : make_float4(0, 0, 0, 0);

    float accf[4][4][4];
    #pragma unroll
    for (int mi = 0; mi < 4; mi++)
        #pragma unroll
        for (int ni = 0; ni < 4; ni++)
            #pragma unroll
            for (int r = 0; r < 4; r++) accf[mi][ni][r] = 0.f;

    As[0][lK + 0][lRow] = to_tf32(pa.x); As[0][lK + 1][lRow] = to_tf32(pa.y);
    As[0][lK + 2][lRow] = to_tf32(pa.z); As[0][lK + 3][lRow] = to_tf32(pa.w);
    Bs[0][lK + 0][lRow] = to_tf32(pb.x); Bs[0][lK + 1][lRow] = to_tf32(pb.y);
    Bs[0][lK + 2][lRow] = to_tf32(pb.z); Bs[0][lK + 3][lRow] = to_tf32(pb.w);
    __syncthreads();

    int buf = 0;
    for (int kt = 0; kt < 32; kt++) {
        bool more = (kt + 1 < 32);
        if (more) {
            pa = *(const float4*)(Aptr + (kt + 1) * 8);
            if (bAct) pb = *(const float4*)(Bptr + (kt + 1) * 8);
        }
        unsigned int af[4][4], bf[4][2];
        #pragma unroll
        for (int mi = 0; mi < 4; mi++) {
            int rm = wm + mi * 16 + g;
            af[mi][0] = __float_as_uint(As[buf][tig][rm]);
            af[mi][1] = __float_as_uint(As[buf][tig][rm + 8]);
            af[mi][2] = __float_as_uint(As[buf][tig + 4][rm]);
            af[mi][3] = __float_as_uint(As[buf][tig + 4][rm + 8]);
        }
        #pragma unroll
        for (int ni = 0; ni < 4; ni++) {
            int cn = wn + ni * 8 + g;
            bf[ni][0] = __float_as_uint(Bs[buf][tig][cn]);
            bf[ni][1] = __float_as_uint(Bs[buf][tig + 4][cn]);
        }
        #pragma unroll
        for (int mi = 0; mi < 4; mi++)
            #pragma unroll
            for (int ni = 0; ni < 4; ni++) {
                asm volatile(
                    "mma.sync.aligned.m16n8k8.row.col.f32.tf32.tf32.f32 "
                    "{%0,%1,%2,%3}, {%4,%5,%6,%7}, {%8,%9}, {%0,%1,%2,%3};\n"
                    : "+f"(accf[mi][ni][0]), "+f"(accf[mi][ni][1]),
                      "+f"(accf[mi][ni][2]), "+f"(accf[mi][ni][3])
                    : "r"(af[mi][0]), "r"(af[mi][1]), "r"(af[mi][2]), "r"(af[mi][3]),
                      "r"(bf[ni][0]), "r"(bf[ni][1]));
            }
        if (more) {
            int nb = buf ^ 1;
            As[nb][lK + 0][lRow] = to_tf32(pa.x); As[nb][lK + 1][lRow] = to_tf32(pa.y);
            As[nb][lK + 2][lRow] = to_tf32(pa.z); As[nb][lK + 3][lRow] = to_tf32(pa.w);
            Bs[nb][lK + 0][lRow] = to_tf32(pb.x); Bs[nb][lK + 1][lRow] = to_tf32(pb.y);
            Bs[nb][lK + 2][lRow] = to_tf32(pb.z); Bs[nb][lK + 3][lRow] = to_tf32(pb.w);
        }
        __syncthreads();
        buf ^= 1;
    }

    if (wn >= 64) return;   // cols >= 64 all invalid (after all syncs)
    #pragma unroll
    for (int mi = 0; mi < 4; mi++) {
        int r0 = m0 + wm + mi * 16 + g;
        #pragma unroll
        for (int ni = 0; ni < 4; ni++) {
            int cc = wn + ni * 8 + 2 * tig;
            if (cc >= 40) continue;
            float2 v0 = make_float2(accf[mi][ni][0], accf[mi][ni][1]);
            float2 v1 = make_float2(accf[mi][ni][2], accf[mi][ni][3]);
            *(float2*)(C + (size_t)r0 * 40 + cc)       = v0;
            *(float2*)(C + (size_t)(r0 + 8) * 40 + cc) = v1;
        }
    }
}

// ========== causal conv1d k=4 + silu, rolling window: 8 positions/thread ====
__global__ __launch_bounds__(256) void conv_silu(
    const float* __restrict__ xzg,
    const float* __restrict__ cw0, const float* __restrict__ cw1,
    const float* __restrict__ cb0, const float* __restrict__ cb1,
    float* __restrict__ xsg)
{
    const int dir = blockIdx.y;
    const float* xz = xzg + (size_t)dir * MR * 512;
    const float* cw = dir ? cw1 : cw0;
    const float* cb = dir ? cb1 : cb0;
    float* xs = xsg + (size_t)dir * MR * DI;
    int idx = blockIdx.x * 256 + threadIdx.x;
    if (idx >= (MR / 8) * 64) return;
    int d4 = idx & 63;
    int mt = idx >> 6;
    int m0 = mt * 8;
    int l0 = m0 % LSEQ;
    int d  = d4 * 4;
    float4 bias = *(const float4*)(cb + d);
    float4 wk[4];
    #pragma unroll
    for (int k = 0; k < 4; k++) {
        wk[k].x = cw[(d + 0) * 4 + k];
        wk[k].y = cw[(d + 1) * 4 + k];
        wk[k].z = cw[(d + 2) * 4 + k];
        wk[k].w = cw[(d + 3) * 4 + k];
    }
    const float4 zero = make_float4(0.f, 0.f, 0.f, 0.f);
    float4 r0 = (l0 >= 3) ? *(const float4*)(xz + (size_t)(m0 - 3) * 512 + d) : zero;
    float4 r1 = (l0 >= 2) ? *(const float4*)(xz + (size_t)(m0 - 2) * 512 + d) : zero;
    float4 r2 = (l0 >= 1) ? *(const float4*)(xz + (size_t)(m0 - 1) * 512 + d) : zero;
    #pragma unroll
    for (int tt = 0; tt < 8; tt++) {
        float4 cur = *(const float4*)(xz + (size_t)(m0 + tt) * 512 + d);
        float4 a = bias;
        a.x = fmaf(r0.x, wk[0].x, a.x); a.y = fmaf(r0.y, wk[0].y, a.y);
        a.z = fmaf(r0.z, wk[0].z, a.z); a.w = fmaf(r0.w, wk[0].w, a.w);
        a.x = fmaf(r1.x, wk[1].x, a.x); a.y = fmaf(r1.y, wk[1].y, a.y);
        a.z = fmaf(r1.z, wk[1].z, a.z); a.w = fmaf(r1.w, wk[1].w, a.w);
        a.x = fmaf(r2.x, wk[2].x, a.x); a.y = fmaf(r2.y, wk[2].y, a.y);
        a.z = fmaf(r2.z, wk[2].z, a.z); a.w = fmaf(r2.w, wk[2].w, a.w);
        a.x = fmaf(cur.x, wk[3].x, a.x); a.y = fmaf(cur.y, wk[3].y, a.y);
        a.z = fmaf(cur.z, wk[3].z, a.z); a.w = fmaf(cur.w, wk[3].w, a.w);
        float4 o;
        o.x = a.x / (1.f + __expf(-a.x));
        o.y = a.y / (1.f + __expf(-a.y));
        o.z = a.z / (1.f + __expf(-a.z));
        o.w = a.w / (1.f + __expf(-a.w));
        *(float4*)(xs + (size_t)(m0 + tt) * DI + d) = o;
        r0 = r1; r1 = r2; r2 = cur;
    }
}

// ========== scan pass A (dt computed inline from dbl) ==========
__global__ __launch_bounds__(256) void scanA(
    const float* __restrict__ xsg, const float* __restrict__ dblg,
    const float* __restrict__ Al0, const float* __restrict__ Al1,
    const float* __restrict__ dtw0, const float* __restrict__ dtw1,
    const float* __restrict__ dtb0, const float* __restrict__ dtb1,
    float* __restrict__ Pcg, float* __restrict__ Hcg)
{
    int d = threadIdx.x, chunk = blockIdx.x, b = blockIdx.y, dir = blockIdx.z;
    const float* xs  = xsg + (size_t)dir * MR * DI;
    const float* dbl = dblg + (size_t)dir * MR * 40;
    const float* Al  = dir ? Al1 : Al0;
    const float* dtw = dir ? dtw1 : dtw0;
    const float* dtb = dir ? dtb1 : dtb0;
    float* Pc = Pcg + (size_t)dir * NC * BATCH * DI * DS;
    float* Hc = Hcg + (size_t)dir * NC * BATCH * DI * DS;
    __shared__ float sB[CL][24];
    int base = b * LSEQ + chunk * CL;
    for (int i = d; i < CL * 24; i += 256) {
        int l = i / 24, n = i % 24;
        sB[l][n] = dbl[(size_t)(base + l) * 40 + n];
    }
    float a[16]; bool fast = true;
    #pragma unroll
    for (int n = 0; n < 16; n++) {
        a[n] = -__expf(Al[d * 16 + n]);
        fast = fast && (fabsf(a[n] + (float)(n + 1)) <= 1e-4f * (n + 1));
    }
    float w[8];
    #pragma unroll
    for (int r = 0; r < 8; r++) w[r] = dtw[d * 8 + r];
    float db = dtb[d];
    __syncthreads();
    float h[16], pp[16];
    #pragma unroll
    for (int n = 0; n < 16; n++) { h[n] = 0.f; pp[n] = 1.f; }
    if (fast) {
        for (int l = 0; l < CL; l++) {
            float s = db;
            #pragma unroll
            for (int r = 0; r < 8; r++) s = fmaf(sB[l][r], w[r], s);
            float dtv = (s > 20.f) ? s : __logf(1.f + __expf(s));
            float xsv = xs[(size_t)(base + l) * DI + d];
            float du = dtv * xsv;
            float e1 = __expf(-dtv);
            float e[16]; e[0] = e1;
            #pragma unroll
            for (int n = 1; n < 16; n++) e[n] = e[n - 1] * e1;
            #pragma unroll
            for (int n = 0; n < 16; n++) {
                pp[n] *= e[n];
                h[n] = fmaf(e[n], h[n], du * sB[l][8 + n]);
            }
        }
    } else {
        for (int l = 0; l < CL; l++) {
            float s = db;
            #pragma unroll
            for (int r = 0; r < 8; r++) s = fmaf(sB[l][r], w[r], s);
            float dtv = (s > 20.f) ? s : __logf(1.f + __expf(s));
            float xsv = xs[(size_t)(base + l) * DI + d];
            float du = dtv * xsv;
            #pragma unroll
            for (int n = 0; n < 16; n++) {
                float e = __expf(dtv * a[n]);
                pp[n] *= e;
                h[n] = fmaf(e, h[n], du * sB[l][8 + n]);
            }
        }
    }
    size_t o = (((size_t)chunk * BATCH + b) * DI + d) * DS;
    #pragma unroll
    for (int n = 0; n < 16; n++) { Pc[o + n] = pp[n]; Hc[o + n] = h[n]; }
}

// ========== scan pass B ==========
__global__ void scanB(const float* __restrict__ Pcg, const float* __restrict__ Hcg,
                      float* __restrict__ Hig)
{
    int dir = blockIdx.y;
    const float* Pc = Pcg + (size_t)dir * NC * BATCH * DI * DS;
    const float* Hc = Hcg + (size_t)dir * NC * BATCH * DI * DS;
    float* Hi = Hig + (size_t)dir * NC * BATCH * DI * DS;
    int idx = blockIdx.x * 256 + threadIdx.x;
    if (idx >= BATCH * DI * DS) return;
    float h = 0.f;
    for (int c = 0; c < NC; c++) {
        size_t o = (size_t)c * (BATCH * DI * DS) + idx;
        Hi[o] = h;
        h = fmaf(Pc[o], h, Hc[o]);
    }
}

// ========== scan pass C + gate fused (dt inline) ==========
__global__ __launch_bounds__(256) void scanC(
    const float* __restrict__ xsg, const float* __restrict__ dblg,
    const float* __restrict__ xzg,
    const float* __restrict__ Al0, const float* __restrict__ Al1,
    const float* __restrict__ dtw0, const float* __restrict__ dtw1,
    const float* __restrict__ dtb0, const float* __restrict__ dtb1,
    const float* __restrict__ D0, const float* __restrict__ D1,
    const float* __restrict__ Hig, float* __restrict__ ysg)
{
    int d = threadIdx.x, chunk = blockIdx.x, b = blockIdx.y, dir = blockIdx.z;
    const float* xs  = xsg + (size_t)dir * MR * DI;
    const float* dbl = dblg + (size_t)dir * MR * 40;
    const float* xz  = xzg + (size_t)dir * MR * 512;
    const float* Al  = dir ? Al1 : Al0;
    const float* dtw = dir ? dtw1 : dtw0;
    const float* dtb = dir ? dtb1 : dtb0;
    const float* Dp  = dir ? D1 : D0;
    const float* Hi  = Hig + (size_t)dir * NC * BATCH * DI * DS;
    float* ys = ysg + (size_t)dir * MR * DI;
    __shared__ float sBC[CL][40];
    int base = b * LSEQ + chunk * CL;
    for (int i = d; i < CL * 40; i += 256) {
        int l = i / 40, j = i % 40;
        sBC[l][j] = dbl[(size_t)(base + l) * 40 + j];
    }
    float a[16]; bool fast = true;
    #pragma unroll
    for (int n = 0; n < 16; n++) {
        a[n] = -__expf(Al[d * 16 + n]);
        fast = fast && (fabsf(a[n] + (float)(n + 1)) <= 1e-4f * (n + 1));
    }
    float w[8];
    #pragma unroll
    for (int r = 0; r < 8; r++) w[r] = dtw[d * 8 + r];
    float db = dtb[d];
    float Dd = Dp[d];
    float h[16];
    size_t o = (((size_t)chunk * BATCH + b) * DI + d) * DS;
    #pragma unroll
    for (int n = 0; n < 16; n++) h[n] = Hi[o + n];
    __syncthreads();
    if (fast) {
        for (int l = 0; l < CL; l++) {
            float s = db;
            #pragma unroll
            for (int r = 0; r < 8; r++) s = fmaf(sBC[l][r], w[r], s);
            float dtv = (s > 20.f) ? s : __logf(1.f + __expf(s));
            float xsv = xs[(size_t)(base + l) * DI + d];
            float zv  = xz[(size_t)(base + l) * 512 + 256 + d];
            float du = dtv * xsv;
            float e1 = __expf(-dtv);
            float e[16]; e[0] = e1;
            #pragma unroll
            for (int n = 1; n < 16; n++) e[n] = e[n - 1] * e1;
            float y = 0.f;
            #pragma unroll
            for (int n = 0; n < 16; n++) {
                h[n] = fmaf(e[n], h[n], du * sBC[l][8 + n]);
                y = fmaf(h[n], sBC[l][24 + n], y);
            }
            float sz = zv / (1.f + __expf(-zv));
            ys[(size_t)(base + l) * DI + d] = (y + xsv * Dd) * sz;
        }
    } else {
        for (int l = 0; l < CL; l++) {
            float s = db;
            #pragma unroll
            for (int r = 0; r < 8; r++) s = fmaf(sBC[l][r], w[r], s);
            float dtv = (s > 20.f) ? s : __logf(1.f + __expf(s));
            float xsv = xs[(size_t)(base + l) * DI + d];
            float zv  = xz[(size_t)(base + l) * 512 + 256 + d];
            float du = dtv * xsv;
            float y = 0.f;
            #pragma unroll
            for (int n = 0; n < 16; n++) {
                float e = __expf(dtv * a[n]);
                h[n] = fmaf(e, h[n], du * sBC[l][8 + n]);
                y = fmaf(h[n], sBC[l][24 + n], y);
            }
            float sz = zv / (1.f + __expf(-zv));
            ys[(size_t)(base + l) * DI + d] = (y + xsv * Dd) * sz;
        }
    }
}

// ========== fuse oh+ov+lf, partial sums ==========
__global__ void fuse_kernel(const float* __restrict__ oh, const float* __restrict__ ov,
                            const float* __restrict__ lf, float* __restrict__ fused,
                            float* __restrict__ psum)
{
    int c = threadIdx.x;
    int pc = blockIdx.x;
    int b  = blockIdx.y;
    float s = 0.f;
    for (int i = 0; i < 32; i++) {
        int p = pc * 32 + i;
        int pv = (p % WWD) * HH + p / WWD;
        float f = oh[((size_t)(b * LSEQ + p)) * 128 + c]
                + ov[((size_t)(b * LSEQ + pv)) * 128 + c]
                + lf[((size_t)(b * PPOS + p)) * 128 + c];
        fused[((size_t)(b * PPOS + p)) * 128 + c] = f;
        s += f;
    }
    psum[((size_t)b * 98 + pc) * 128 + c] = s;
}

// ========== final: channel attention (recomputed per block) + residual ==========
__global__ __launch_bounds__(256) void final_attn(
    const float* __restrict__ psum,
    const float* __restrict__ fc1, const float* __restrict__ fc2,
    const float* __restrict__ fused, const float* __restrict__ x,
    float* __restrict__ out)
{
    __shared__ float spart[2][128];
    __shared__ float sm[128];
    __shared__ float t1[32];
    __shared__ float satn[128];
    __shared__ float sf[128][33];
    int t = threadIdx.x;
    int p0 = blockIdx.x * 32;
    int b  = blockIdx.y;
    {
        int c = t & 127, half = t >> 7;
        float s = 0.f;
        for (int pc = half * 49; pc < half * 49 + 49; pc++)
            s += psum[((size_t)b * 98 + pc) * 128 + c];
        spart[half][c] = s;
    }
    __syncthreads();
    if (t < 128) sm[t] = (spart[0][t] + spart[1][t]) * (1.f / (float)PPOS);
    __syncthreads();
    if (t < 32) {
        float acc = 0.f;
        #pragma unroll 4
        for (int c = 0; c < 128; c++) acc = fmaf(sm[c], fc1[t * 128 + c], acc);
        t1[t] = fmaxf(acc, 0.f);
    }
    __syncthreads();
    if (t < 128) {
        float acc = 0.f;
        #pragma unroll
        for (int i = 0; i < 32; i++) acc = fmaf(t1[i], fc2[t * 32 + i], acc);
        satn[t] = 1.f / (1.f + __expf(-acc));
    }
    {
        int c = t & 127, ph = t >> 7;
        #pragma unroll
        for (int pass = 0; pass < 16; pass++) {
            int pl = pass * 2 + ph;
            sf[c][pl] = fused[((size_t)(b * PPOS + p0 + pl)) * 128 + c];
        }
    }
    __syncthreads();
    int pl = t & 31, c8 = t >> 5;
    #pragma unroll
    for (int pass = 0; pass < 16; pass++) {
        int c = pass * 8 + c8;
        size_t gi = ((size_t)(b * 128 + c)) * PPOS + p0 + pl;
        out[gi] = sf[c][pl] * satn[c] + x[gi];
    }
}

// ============================================================================
extern "C" void kernel_launch(void* const* d_in, const int* in_sizes, int n_in,
                              void* d_out, int out_size)
{
    const float* x       = (const float*)d_in[0];
    const float* norm_hw = (const float*)d_in[1];
    const float* norm_hb = (const float*)d_in[2];
    const float* norm_vw = (const float*)d_in[3];
    const float* norm_vb = (const float*)d_in[4];
    const float* dw_w    = (const float*)d_in[5];
    const float* dw_b    = (const float*)d_in[6];
    const float* pw_w    = (const float*)d_in[7];
    const float* pw_b    = (const float*)d_in[8];
    const float* in_w0    = (const float*)d_in[9];
    const float* conv_w0  = (const float*)d_in[10];
    const float* conv_b0  = (const float*)d_in[11];
    const float* xproj_w0 = (const float*)d_in[12];
    const float* dt_w0    = (const float*)d_in[13];
    const float* dt_b0    = (const float*)d_in[14];
    const float* A_log0   = (const float*)d_in[15];
    const float* D0       = (const float*)d_in[16];
    const float* out_w0   = (const float*)d_in[17];
    const float* in_w1    = (const float*)d_in[18];
    const float* conv_w1  = (const float*)d_in[19];
    const float* conv_b1  = (const float*)d_in[20];
    const float* xproj_w1 = (const float*)d_in[21];
    const float* dt_w1    = (const float*)d_in[22];
    const float* dt_b1    = (const float*)d_in[23];
    const float* A_log1   = (const float*)d_in[24];
    const float* D1       = (const float*)d_in[25];
    const float* out_w1   = (const float*)d_in[26];
    const float* fc1     = (const float*)d_in[27];
    const float* fc2     = (const float*)d_in[28];

    void* p;
    cudaGetSymbolAddress(&p, g_xnorm); float* xnorm = (float*)p;
    cudaGetSymbolAddress(&p, g_xz);    float* xz    = (float*)p;
    cudaGetSymbolAddress(&p, g_xs);    float* xs    = (float*)p;
    cudaGetSymbolAddress(&p, g_dbl);   float* dbl   = (float*)p;
    cudaGetSymbolAddress(&p, g_ys);    float* ys    = (float*)p;
    cudaGetSymbolAddress(&p, g_o);     float* ob    = (float*)p;
    cudaGetSymbolAddress(&p, g_g);     float* gbuf  = (float*)p;
    cudaGetSymbolAddress(&p, g_lf);    float* lfb   = (float*)p;
    cudaGetSymbolAddress(&p, g_fused); float* fused = (float*)p;
    cudaGetSymbolAddress(&p, g_Pc);    float* Pc    = (float*)p;
    cudaGetSymbolAddress(&p, g_Hc);    float* Hc    = (float*)p;
    cudaGetSymbolAddress(&p, g_Hi);    float* Hi    = (float*)p;
    cudaGetSymbolAddress(&p, g_psum);  float* psum  = (float*)p;

    // prep: layernorm (both layouts) + local-feature dwconv+gelu
    prep_kernel<<<dim3(98, 2), 256>>>(x, norm_hw, norm_hb, norm_vw, norm_vb,
                                      dw_w, dw_b,
                                      xnorm, xnorm + (size_t)MR * CDIM, gbuf);
    // in_proj (z<2) + pointwise conv (z=2), all TF32, one launch
    gemm_tf32_multi<<<dim3(4, 49, 3), 256>>>(xnorm, in_w0, in_w1, xz,
                                             gbuf, pw_w, pw_b, lfb);
    // conv + silu (rolling window, 8 pos/thread)
    conv_silu<<<dim3((MR / 8) * 64 / 256, 2), 256>>>(xz, conv_w0, conv_w1,
                                                     conv_b0, conv_b1, xs);
    // x_proj: TF32 tensor cores (dt computed inline in scans)
    xproj_tf32<<<dim3(1, 49, 2), 256>>>(xs, xproj_w0, xproj_w1, dbl);
    // selective scan (dt inline)
    scanA<<<dim3(NC, BATCH, 2), 256>>>(xs, dbl, A_log0, A_log1,
                                       dt_w0, dt_w1, dt_b0, dt_b1, Pc, Hc);
    scanB<<<dim3(32, 2), 256>>>(Pc, Hc, Hi);
    scanC<<<dim3(NC, BATCH, 2), 256>>>(xs, dbl, xz, A_log0, A_log1,
                                       dt_w0, dt_w1, dt_b0, dt_b1, D0, D1, Hi, ys);
    // out_proj: TF32 tensor cores, 128x128 tiles, 98 blocks
    gemm_tf32<<<dim3(1, 49, 2), 256>>>(ys, out_w0, out_w1, nullptr, ob,
                                       128, 256, (size_t)MR * DI, (size_t)MR * CDIM);
    // fuse + attention + residual
    fuse_kernel<<<dim3(98, 2), 128>>>(ob, ob + (size_t)MR * CDIM, lfb, fused, psum);
    final_attn<<<dim3(98, 2), 256>>>(psum, fc1, fc2, fused, x, (float*)d_out);
}

// round 15
// speedup vs baseline: 1.0432x; 1.0346x over previous
#include <cuda_runtime.h>
#include <cuda_bf16.h>
#include <cstddef>
#include <cstdint>

#define BATCH 2
#define CDIM  128
#define HH    56
#define WWD   56
#define PPOS  3136
#define LSEQ  3136
#define MR    6272
#define DI    256
#define DS    16
#define NC    49
#define CL    64

// ---------------- scratch ----------------
__device__ __align__(16) float g_xnorm[2][MR * CDIM];
__device__ __align__(16) float g_xz   [2][MR * 512];
__device__ __align__(16) float g_xs   [2][MR * DI];
__device__ __align__(16) float g_dbl  [2][MR * 40];
__device__ __align__(16) float g_ys   [2][MR * DI];
__device__ __align__(16) float g_o    [2][MR * CDIM];
__device__ __align__(16) float g_g    [MR * CDIM];
__device__ __align__(16) float g_lf   [MR * CDIM];
__device__ __align__(16) float g_fused[MR * CDIM];
__device__ __align__(16) float g_Pc [2][NC * BATCH * DI * DS];
__device__ __align__(16) float g_Hc [2][NC * BATCH * DI * DS];
__device__ __align__(16) float g_Hi [2][NC * BATCH * DI * DS];
__device__ __align__(16) float g_psum[BATCH * 98 * CDIM];

__device__ __forceinline__ float to_tf32(float x) {
    unsigned int u;
    asm("cvt.rna.tf32.f32 %0, %1;" : "=r"(u) : "f"(x));
    return __uint_as_float(u);
}

// ========== prep: LayerNorm (both layouts) + depthwise 3x3 + GELU ==========
__global__ __launch_bounds__(256) void prep_kernel(
    const float* __restrict__ x,
    const float* __restrict__ hw, const float* __restrict__ hb,
    const float* __restrict__ vw, const float* __restrict__ vb,
    const float* __restrict__ dww, const float* __restrict__ dwb,
    float* __restrict__ xh, float* __restrict__ xv, float* __restrict__ g)
{
    __shared__ float sx[128][33];
    __shared__ float part[8][33];
    __shared__ float partq[8][33];
    __shared__ float mu[32], rs[32];
    __shared__ float sg[128][33];
    int t = threadIdx.x;
    int p0 = blockIdx.x * 32;
    int b  = blockIdx.y;
    int pl = t & 31, c8 = t >> 5;
    float s = 0.f, sq = 0.f;
    #pragma unroll
    for (int pass = 0; pass < 16; pass++) {
        int c = pass * 8 + c8;
        float v = x[((size_t)(b * 128 + c)) * PPOS + p0 + pl];
        sx[c][pl] = v;
        s += v; sq += v * v;
    }
    part[c8][pl] = s; partq[c8][pl] = sq;
    __syncthreads();
    if (t < 32) {
        float S = 0.f, Q = 0.f;
        #pragma unroll
        for (int r = 0; r < 8; r++) { S += part[r][t]; Q += partq[r][t]; }
        float mean = S * (1.f / 128.f);
        float var  = Q * (1.f / 128.f) - mean * mean;
        mu[t] = mean;
        rs[t] = rsqrtf(var + 1e-5f);
    }
    __syncthreads();
    {
        int c = t & 127, ph = t >> 7;
        float whh = hw[c], bhh = hb[c], wvv = vw[c], bvv = vb[c];
        #pragma unroll
        for (int pass = 0; pass < 16; pass++) {
            int pl2 = pass * 2 + ph;
            int p = p0 + pl2;
            float xc = (sx[c][pl2] - mu[pl2]) * rs[pl2];
            int h = p / WWD, w = p % WWD;
            xh[((size_t)b * LSEQ + p) * 128 + c]            = xc * whh + bhh;
            xv[((size_t)b * LSEQ + (w * HH + h)) * 128 + c] = xc * wvv + bvv;
        }
    }
    {
        int p = p0 + pl;
        int h = p / WWD, w = p % WWD;
        #pragma unroll
        for (int pass = 0; pass < 16; pass++) {
            int c = pass * 8 + c8;
            const float* xb = x + ((size_t)(b * 128 + c)) * PPOS;
            float acc = dwb[c];
            #pragma unroll
            for (int kh = 0; kh < 3; kh++) {
                int hh = h + kh - 1;
                if (hh < 0 || hh >= HH) continue;
                #pragma unroll
                for (int kw = 0; kw < 3; kw++) {
                    int ww = w + kw - 1;
                    if (ww < 0 || ww >= WWD) continue;
                    acc = fmaf(xb[hh * WWD + ww], dww[c * 9 + kh * 3 + kw], acc);
                }
            }
            sg[c][pl] = 0.5f * acc * (1.f + erff(acc * 0.70710678118654752f));
        }
    }
    __syncthreads();
    {
        int c = t & 127, ph = t >> 7;
        #pragma unroll
        for (int pass = 0; pass < 16; pass++) {
            int pl2 = pass * 2 + ph;
            g[((size_t)(b * PPOS + p0 + pl2)) * 128 + c] = sg[c][pl2];
        }
    }
}

// ========== TF32 GEMM core (device func): 128x128 block, 8 warps ==========
__device__ __forceinline__ void gemm_tf32_body(
    const float* __restrict__ A, const float* __restrict__ Bw,
    const float* __restrict__ bias, float* __restrict__ C,
    int m0, int n0, int N, int K)
{
    __shared__ float As[2][8][136];
    __shared__ float Bs[2][8][136];

    const int t    = threadIdx.x;
    const int lane = t & 31;
    const int wid  = t >> 5;
    const int g    = lane >> 2;
    const int tig  = lane & 3;
    const int wm   = (wid & 1) * 64;
    const int wn   = (wid >> 1) * 32;

    const int lRow = t >> 1;
    const int lK   = (t & 1) * 4;

    const float* Aptr = A + (size_t)(m0 + lRow) * K + lK;
    const float* Bptr = Bw + (size_t)(n0 + lRow) * K + lK;

    float4 pa = *(const float4*)Aptr;
    float4 pb = *(const float4*)Bptr;

    float acc[4][4][4];
    #pragma unroll
    for (int mi = 0; mi < 4; mi++)
        #pragma unroll
        for (int ni = 0; ni < 4; ni++)
            #pragma unroll
            for (int r = 0; r < 4; r++) acc[mi][ni][r] = 0.f;

    As[0][lK + 0][lRow] = to_tf32(pa.x); As[0][lK + 1][lRow] = to_tf32(pa.y);
    As[0][lK + 2][lRow] = to_tf32(pa.z); As[0][lK + 3][lRow] = to_tf32(pa.w);
    Bs[0][lK + 0][lRow] = to_tf32(pb.x); Bs[0][lK + 1][lRow] = to_tf32(pb.y);
    Bs[0][lK + 2][lRow] = to_tf32(pb.z); Bs[0][lK + 3][lRow] = to_tf32(pb.w);
    __syncthreads();

    const int nt = K >> 3;
    int buf = 0;
    for (int kt = 0; kt < nt; kt++) {
        bool more = (kt + 1 < nt);
        if (more) {
            pa = *(const float4*)(Aptr + (kt + 1) * 8);
            pb = *(const float4*)(Bptr + (kt + 1) * 8);
        }
        unsigned int af[4][4], bf[4][2];
        #pragma unroll
        for (int mi = 0; mi < 4; mi++) {
            int rm = wm + mi * 16 + g;
            af[mi][0] = __float_as_uint(As[buf][tig][rm]);
            af[mi][1] = __float_as_uint(As[buf][tig][rm + 8]);
            af[mi][2] = __float_as_uint(As[buf][tig + 4][rm]);
            af[mi][3] = __float_as_uint(As[buf][tig + 4][rm + 8]);
        }
        #pragma unroll
        for (int ni = 0; ni < 4; ni++) {
            int cn = wn + ni * 8 + g;
            bf[ni][0] = __float_as_uint(Bs[buf][tig][cn]);
            bf[ni][1] = __float_as_uint(Bs[buf][tig + 4][cn]);
        }
        #pragma unroll
        for (int mi = 0; mi < 4; mi++)
            #pragma unroll
            for (int ni = 0; ni < 4; ni++) {
                asm volatile(
                    "mma.sync.aligned.m16n8k8.row.col.f32.tf32.tf32.f32 "
                    "{%0,%1,%2,%3}, {%4,%5,%6,%7}, {%8,%9}, {%0,%1,%2,%3};\n"
                    : "+f"(acc[mi][ni][0]), "+f"(acc[mi][ni][1]),
                      "+f"(acc[mi][ni][2]), "+f"(acc[mi][ni][3])
                    : "r"(af[mi][0]), "r"(af[mi][1]), "r"(af[mi][2]), "r"(af[mi][3]),
                      "r"(bf[ni][0]), "r"(bf[ni][1]));
            }
        if (more) {
            int nb = buf ^ 1;
            As[nb][lK + 0][lRow] = to_tf32(pa.x); As[nb][lK + 1][lRow] = to_tf32(pa.y);
            As[nb][lK + 2][lRow] = to_tf32(pa.z); As[nb][lK + 3][lRow] = to_tf32(pa.w);
            Bs[nb][lK + 0][lRow] = to_tf32(pb.x); Bs[nb][lK + 1][lRow] = to_tf32(pb.y);
            Bs[nb][lK + 2][lRow] = to_tf32(pb.z); Bs[nb][lK + 3][lRow] = to_tf32(pb.w);
        }
        __syncthreads();
        buf ^= 1;
    }

    #pragma unroll
    for (int mi = 0; mi < 4; mi++) {
        int r0 = m0 + wm + mi * 16 + g;
        #pragma unroll
        for (int ni = 0; ni < 4; ni++) {
            int cc = n0 + wn + ni * 8 + 2 * tig;
            float2 bb = make_float2(0.f, 0.f);
            if (bias) bb = *(const float2*)(bias + cc);
            float2 v0 = make_float2(acc[mi][ni][0] + bb.x, acc[mi][ni][1] + bb.y);
            float2 v1 = make_float2(acc[mi][ni][2] + bb.x, acc[mi][ni][3] + bb.y);
            *(float2*)(C + (size_t)r0 * N + cc)       = v0;
            *(float2*)(C + (size_t)(r0 + 8) * N + cc) = v1;
        }
    }
}

// generic TF32 GEMM (used for out_proj)
__global__ __launch_bounds__(256) void gemm_tf32(
    const float* __restrict__ Abase,
    const float* __restrict__ B0, const float* __restrict__ B1,
    const float* __restrict__ bias,
    float* __restrict__ Cbase,
    int N, int K, size_t dsA, size_t dsC)
{
    const int dir = blockIdx.z;
    gemm_tf32_body(Abase + (size_t)dir * dsA, dir ? B1 : B0, bias,
                   Cbase + (size_t)dir * dsC,
                   blockIdx.y * 128, blockIdx.x * 128, N, K);
}

// merged: z<2 -> in_proj (N=512,K=128), z==2 -> pointwise conv (N=128,K=128)
__global__ __launch_bounds__(256) void gemm_tf32_multi(
    const float* __restrict__ xnorm,
    const float* __restrict__ inw0, const float* __restrict__ inw1,
    float* __restrict__ xz,
    const float* __restrict__ gbuf, const float* __restrict__ pww,
    const float* __restrict__ pwb, float* __restrict__ lfb)
{
    const int z = blockIdx.z;
    if (z < 2) {
        gemm_tf32_body(xnorm + (size_t)z * MR * CDIM, z ? inw1 : inw0, nullptr,
                       xz + (size_t)z * MR * 512,
                       blockIdx.y * 128, blockIdx.x * 128, 512, 128);
    } else {
        if (blockIdx.x != 0) return;
        gemm_tf32_body(gbuf, pww, pwb, lfb, blockIdx.y * 128, 0, 128, 128);
    }
}

// ========== x_proj GEMM via TF32: M-tile=64, N=40, 196 blocks ==========
// 8 warps as 4(M)x2(N); warp tile m16 x n32; acc[4][4] per thread.
__global__ __launch_bounds__(256) void xproj_tf32(
    const float* __restrict__ xsg,
    const float* __restrict__ W0, const float* __restrict__ W1,
    float* __restrict__ dblg)
{
    const int dir = blockIdx.z;
    const float* A  = xsg + (size_t)dir * MR * DI;
    const float* Bw = dir ? W1 : W0;
    float* C = dblg + (size_t)dir * MR * 40;
    const int m0 = blockIdx.y * 64;
    const int K = 256;

    __shared__ float As[2][8][72];   // 72 mod 32 == 8 -> conflict-free frag loads
    __shared__ float Bs[2][8][72];

    const int t    = threadIdx.x;
    const int lane = t & 31;
    const int wid  = t >> 5;
    const int g    = lane >> 2;
    const int tig  = lane & 3;
    const int wm   = (wid & 3) * 16;   // 0,16,32,48
    const int wn   = (wid >> 2) * 32;  // 0,32

    // A loader: row = t&63 (64 rows), k = (t>>6)*2 (float2)
    const int aRow = t & 63;
    const int aK   = (t >> 6) * 2;
    // B loader: rows 0..39, 160 active threads, k = (t&3)*2 (float2)
    const int bRow = t >> 2;
    const int bK   = (t & 3) * 2;
    const bool bAct = bRow < 40;

    const float* Aptr = A + (size_t)(m0 + aRow) * K + aK;
    const float* Bptr = Bw + (size_t)(bAct ? bRow : 0) * K + bK;

    float2 pa = *(const float2*)Aptr;
    float2 pb = bAct ? *(const float2*)Bptr : make_float2(0.f, 0.f);

    float acc[4][4];
    #pragma unroll
    for (int ni = 0; ni < 4; ni++)
        #pragma unroll
        for (int r = 0; r < 4; r++) acc[ni][r] = 0.f;

    As[0][aK + 0][aRow] = to_tf32(pa.x); As[0][aK + 1][aRow] = to_tf32(pa.y);
    if (bAct) {
        Bs[0][bK + 0][bRow] = to_tf32(pb.x); Bs[0][bK + 1][bRow] = to_tf32(pb.y);
    }
    __syncthreads();

    int buf = 0;
    for (int kt = 0; kt < 32; kt++) {
        bool more = (kt + 1 < 32);
        if (more) {
            pa = *(const float2*)(Aptr + (kt + 1) * 8);
            if (bAct) pb = *(const float2*)(Bptr + (kt + 1) * 8);
        }
        unsigned int af[4], bf[4][2];
        {
            int rm = wm + g;
            af[0] = __float_as_uint(As[buf][tig][rm]);
            af[1] = __float_as_uint(As[buf][tig][rm + 8]);
            af[2] = __float_as_uint(As[buf][tig + 4][rm]);
            af[3] = __float_as_uint(As[buf][tig + 4][rm + 8]);
        }
        #pragma unroll
        for (int ni = 0; ni < 4; ni++) {
            int cn = wn + ni * 8 + g;
            bf[ni][0] = __float_as_uint(Bs[buf][tig][cn]);
            bf[ni][1] = __float_as_uint(Bs[buf][tig + 4][cn]);
        }
        #pragma unroll
        for (int ni = 0; ni < 4; ni++) {
            asm volatile(
                "mma.sync.aligned.m16n8k8.row.col.f32.tf32.tf32.f32 "
                "{%0,%1,%2,%3}, {%4,%5,%6,%7}, {%8,%9}, {%0,%1,%2,%3};\n"
                : "+f"(acc[ni][0]), "+f"(acc[ni][1]),
                  "+f"(acc[ni][2]), "+f"(acc[ni][3])
                : "r"(af[0]), "r"(af[1]), "r"(af[2]), "r"(af[3]),
                  "r"(bf[ni][0]), "r"(bf[ni][1]));
        }
        if (more) {
            int nb = buf ^ 1;
            As[nb][aK + 0][aRow] = to_tf32(pa.x); As[nb][aK + 1][aRow] = to_tf32(pa.y);
            if (bAct) {
                Bs[nb][bK + 0][bRow] = to_tf32(pb.x); Bs[nb][bK + 1][bRow] = to_tf32(pb.y);
            }
        }
        __syncthreads();
        buf ^= 1;
    }

    int r0 = m0 + wm + g;
    #pragma unroll
    for (int ni = 0; ni < 4; ni++) {
        int cc = wn + ni * 8 + 2 * tig;
        if (cc >= 40) continue;
        float2 v0 = make_float2(acc[ni][0], acc[ni][1]);
        float2 v1 = make_float2(acc[ni][2], acc[ni][3]);
        *(float2*)(C + (size_t)r0 * 40 + cc)       = v0;
        *(float2*)(C + (size_t)(r0 + 8) * 40 + cc) = v1;
    }
}

// ========== causal conv1d k=4 + silu, rolling window: 8 positions/thread ====
__global__ __launch_bounds__(256) void conv_silu(
    const float* __restrict__ xzg,
    const float* __restrict__ cw0, const float* __restrict__ cw1,
    const float* __restrict__ cb0, const float* __restrict__ cb1,
    float* __restrict__ xsg)
{
    const int dir = blockIdx.y;
    const float* xz = xzg + (size_t)dir * MR * 512;
    const float* cw = dir ? cw1 : cw0;
    const float* cb = dir ? cb1 : cb0;
    float* xs = xsg + (size_t)dir * MR * DI;
    int idx = blockIdx.x * 256 + threadIdx.x;
    if (idx >= (MR / 8) * 64) return;
    int d4 = idx & 63;
    int mt = idx >> 6;
    int m0 = mt * 8;
    int l0 = m0 % LSEQ;
    int d  = d4 * 4;
    float4 bias = *(const float4*)(cb + d);
    float4 wk[4];
    #pragma unroll
    for (int k = 0; k < 4; k++) {
        wk[k].x = cw[(d + 0) * 4 + k];
        wk[k].y = cw[(d + 1) * 4 + k];
        wk[k].z = cw[(d + 2) * 4 + k];
        wk[k].w = cw[(d + 3) * 4 + k];
    }
    const float4 zero = make_float4(0.f, 0.f, 0.f, 0.f);
    float4 r0 = (l0 >= 3) ? *(const float4*)(xz + (size_t)(m0 - 3) * 512 + d) : zero;
    float4 r1 = (l0 >= 2) ? *(const float4*)(xz + (size_t)(m0 - 2) * 512 + d) : zero;
    float4 r2 = (l0 >= 1) ? *(const float4*)(xz + (size_t)(m0 - 1) * 512 + d) : zero;
    #pragma unroll
    for (int tt = 0; tt < 8; tt++) {
        float4 cur = *(const float4*)(xz + (size_t)(m0 + tt) * 512 + d);
        float4 a = bias;
        a.x = fmaf(r0.x, wk[0].x, a.x); a.y = fmaf(r0.y, wk[0].y, a.y);
        a.z = fmaf(r0.z, wk[0].z, a.z); a.w = fmaf(r0.w, wk[0].w, a.w);
        a.x = fmaf(r1.x, wk[1].x, a.x); a.y = fmaf(r1.y, wk[1].y, a.y);
        a.z = fmaf(r1.z, wk[1].z, a.z); a.w = fmaf(r1.w, wk[1].w, a.w);
        a.x = fmaf(r2.x, wk[2].x, a.x); a.y = fmaf(r2.y, wk[2].y, a.y);
        a.z = fmaf(r2.z, wk[2].z, a.z); a.w = fmaf(r2.w, wk[2].w, a.w);
        a.x = fmaf(cur.x, wk[3].x, a.x); a.y = fmaf(cur.y, wk[3].y, a.y);
        a.z = fmaf(cur.z, wk[3].z, a.z); a.w = fmaf(cur.w, wk[3].w, a.w);
        float4 o;
        o.x = a.x / (1.f + __expf(-a.x));
        o.y = a.y / (1.f + __expf(-a.y));
        o.z = a.z / (1.f + __expf(-a.z));
        o.w = a.w / (1.f + __expf(-a.w));
        *(float4*)(xs + (size_t)(m0 + tt) * DI + d) = o;
        r0 = r1; r1 = r2; r2 = cur;
    }
}

// ========== scan pass A (dt computed inline from dbl) ==========
__global__ __launch_bounds__(256) void scanA(
    const float* __restrict__ xsg, const float* __restrict__ dblg,
    const float* __restrict__ Al0, const float* __restrict__ Al1,
    const float* __restrict__ dtw0, const float* __restrict__ dtw1,
    const float* __restrict__ dtb0, const float* __restrict__ dtb1,
    float* __restrict__ Pcg, float* __restrict__ Hcg)
{
    int d = threadIdx.x, chunk = blockIdx.x, b = blockIdx.y, dir = blockIdx.z;
    const float* xs  = xsg + (size_t)dir * MR * DI;
    const float* dbl = dblg + (size_t)dir * MR * 40;
    const float* Al  = dir ? Al1 : Al0;
    const float* dtw = dir ? dtw1 : dtw0;
    const float* dtb = dir ? dtb1 : dtb0;
    float* Pc = Pcg + (size_t)dir * NC * BATCH * DI * DS;
    float* Hc = Hcg + (size_t)dir * NC * BATCH * DI * DS;
    __shared__ float sB[CL][24];
    int base = b * LSEQ + chunk * CL;
    for (int i = d; i < CL * 24; i += 256) {
        int l = i / 24, n = i % 24;
        sB[l][n] = dbl[(size_t)(base + l) * 40 + n];
    }
    float a[16]; bool fast = true;
    #pragma unroll
    for (int n = 0; n < 16; n++) {
        a[n] = -__expf(Al[d * 16 + n]);
        fast = fast && (fabsf(a[n] + (float)(n + 1)) <= 1e-4f * (n + 1));
    }
    float w[8];
    #pragma unroll
    for (int r = 0; r < 8; r++) w[r] = dtw[d * 8 + r];
    float db = dtb[d];
    __syncthreads();
    float h[16], pp[16];
    #pragma unroll
    for (int n = 0; n < 16; n++) { h[n] = 0.f; pp[n] = 1.f; }
    if (fast) {
        for (int l = 0; l < CL; l++) {
            float s = db;
            #pragma unroll
            for (int r = 0; r < 8; r++) s = fmaf(sB[l][r], w[r], s);
            float dtv = (s > 20.f) ? s : __logf(1.f + __expf(s));
            float xsv = xs[(size_t)(base + l) * DI + d];
            float du = dtv * xsv;
            float e1 = __expf(-dtv);
            float e[16]; e[0] = e1;
            #pragma unroll
            for (int n = 1; n < 16; n++) e[n] = e[n - 1] * e1;
            #pragma unroll
            for (int n = 0; n < 16; n++) {
                pp[n] *= e[n];
                h[n] = fmaf(e[n], h[n], du * sB[l][8 + n]);
            }
        }
    } else {
        for (int l = 0; l < CL; l++) {
            float s = db;
            #pragma unroll
            for (int r = 0; r < 8; r++) s = fmaf(sB[l][r], w[r], s);
            float dtv = (s > 20.f) ? s : __logf(1.f + __expf(s));
            float xsv = xs[(size_t)(base + l) * DI + d];
            float du = dtv * xsv;
            #pragma unroll
            for (int n = 0; n < 16; n++) {
                float e = __expf(dtv * a[n]);
                pp[n] *= e;
                h[n] = fmaf(e, h[n], du * sB[l][8 + n]);
            }
        }
    }
    size_t o = (((size_t)chunk * BATCH + b) * DI + d) * DS;
    #pragma unroll
    for (int n = 0; n < 16; n++) { Pc[o + n] = pp[n]; Hc[o + n] = h[n]; }
}

// ========== scan pass B ==========
__global__ void scanB(const float* __restrict__ Pcg, const float* __restrict__ Hcg,
                      float* __restrict__ Hig)
{
    int dir = blockIdx.y;
    const float* Pc = Pcg + (size_t)dir * NC * BATCH * DI * DS;
    const float* Hc = Hcg + (size_t)dir * NC * BATCH * DI * DS;
    float* Hi = Hig + (size_t)dir * NC * BATCH * DI * DS;
    int idx = blockIdx.x * 256 + threadIdx.x;
    if (idx >= BATCH * DI * DS) return;
    float h = 0.f;
    for (int c = 0; c < NC; c++) {
        size_t o = (size_t)c * (BATCH * DI * DS) + idx;
        Hi[o] = h;
        h = fmaf(Pc[o], h, Hc[o]);
    }
}

// ========== scan pass C + gate fused (dt inline) ==========
__global__ __launch_bounds__(256) void scanC(
    const float* __restrict__ xsg, const float* __restrict__ dblg,
    const float* __restrict__ xzg,
    const float* __restrict__ Al0, const float* __restrict__ Al1,
    const float* __restrict__ dtw0, const float* __restrict__ dtw1,
    const float* __restrict__ dtb0, const float* __restrict__ dtb1,
    const float* __restrict__ D0, const float* __restrict__ D1,
    const float* __restrict__ Hig, float* __restrict__ ysg)
{
    int d = threadIdx.x, chunk = blockIdx.x, b = blockIdx.y, dir = blockIdx.z;
    const float* xs  = xsg + (size_t)dir * MR * DI;
    const float* dbl = dblg + (size_t)dir * MR * 40;
    const float* xz  = xzg + (size_t)dir * MR * 512;
    const float* Al  = dir ? Al1 : Al0;
    const float* dtw = dir ? dtw1 : dtw0;
    const float* dtb = dir ? dtb1 : dtb0;
    const float* Dp  = dir ? D1 : D0;
    const float* Hi  = Hig + (size_t)dir * NC * BATCH * DI * DS;
    float* ys = ysg + (size_t)dir * MR * DI;
    __shared__ float sBC[CL][40];
    int base = b * LSEQ + chunk * CL;
    for (int i = d; i < CL * 40; i += 256) {
        int l = i / 40, j = i % 40;
        sBC[l][j] = dbl[(size_t)(base + l) * 40 + j];
    }
    float a[16]; bool fast = true;
    #pragma unroll
    for (int n = 0; n < 16; n++) {
        a[n] = -__expf(Al[d * 16 + n]);
        fast = fast && (fabsf(a[n] + (float)(n + 1)) <= 1e-4f * (n + 1));
    }
    float w[8];
    #pragma unroll
    for (int r = 0; r < 8; r++) w[r] = dtw[d * 8 + r];
    float db = dtb[d];
    float Dd = Dp[d];
    float h[16];
    size_t o = (((size_t)chunk * BATCH + b) * DI + d) * DS;
    #pragma unroll
    for (int n = 0; n < 16; n++) h[n] = Hi[o + n];
    __syncthreads();
    if (fast) {
        for (int l = 0; l < CL; l++) {
            float s = db;
            #pragma unroll
            for (int r = 0; r < 8; r++) s = fmaf(sBC[l][r], w[r], s);
            float dtv = (s > 20.f) ? s : __logf(1.f + __expf(s));
            float xsv = xs[(size_t)(base + l) * DI + d];
            float zv  = xz[(size_t)(base + l) * 512 + 256 + d];
            float du = dtv * xsv;
            float e1 = __expf(-dtv);
            float e[16]; e[0] = e1;
            #pragma unroll
            for (int n = 1; n < 16; n++) e[n] = e[n - 1] * e1;
            float y = 0.f;
            #pragma unroll
            for (int n = 0; n < 16; n++) {
                h[n] = fmaf(e[n], h[n], du * sBC[l][8 + n]);
                y = fmaf(h[n], sBC[l][24 + n], y);
            }
            float sz = zv / (1.f + __expf(-zv));
            ys[(size_t)(base + l) * DI + d] = (y + xsv * Dd) * sz;
        }
    } else {
        for (int l = 0; l < CL; l++) {
            float s = db;
            #pragma unroll
            for (int r = 0; r < 8; r++) s = fmaf(sBC[l][r], w[r], s);
            float dtv = (s > 20.f) ? s : __logf(1.f + __expf(s));
            float xsv = xs[(size_t)(base + l) * DI + d];
            float zv  = xz[(size_t)(base + l) * 512 + 256 + d];
            float du = dtv * xsv;
            float y = 0.f;
            #pragma unroll
            for (int n = 0; n < 16; n++) {
                float e = __expf(dtv * a[n]);
                h[n] = fmaf(e, h[n], du * sBC[l][8 + n]);
                y = fmaf(h[n], sBC[l][24 + n], y);
            }
            float sz = zv / (1.f + __expf(-zv));
            ys[(size_t)(base + l) * DI + d] = (y + xsv * Dd) * sz;
        }
    }
}

// ========== fuse oh+ov+lf, partial sums ==========
__global__ void fuse_kernel(const float* __restrict__ oh, const float* __restrict__ ov,
                            const float* __restrict__ lf, float* __restrict__ fused,
                            float* __restrict__ psum)
{
    int c = threadIdx.x;
    int pc = blockIdx.x;
    int b  = blockIdx.y;
    float s = 0.f;
    for (int i = 0; i < 32; i++) {
        int p = pc * 32 + i;
        int pv = (p % WWD) * HH + p / WWD;
        float f = oh[((size_t)(b * LSEQ + p)) * 128 + c]
                + ov[((size_t)(b * LSEQ + pv)) * 128 + c]
                + lf[((size_t)(b * PPOS + p)) * 128 + c];
        fused[((size_t)(b * PPOS + p)) * 128 + c] = f;
        s += f;
    }
    psum[((size_t)b * 98 + pc) * 128 + c] = s;
}

// ========== final: channel attention (recomputed per block) + residual ==========
__global__ __launch_bounds__(256) void final_attn(
    const float* __restrict__ psum,
    const float* __restrict__ fc1, const float* __restrict__ fc2,
    const float* __restrict__ fused, const float* __restrict__ x,
    float* __restrict__ out)
{
    __shared__ float spart[2][128];
    __shared__ float sm[128];
    __shared__ float t1[32];
    __shared__ float satn[128];
    __shared__ float sf[128][33];
    int t = threadIdx.x;
    int p0 = blockIdx.x * 32;
    int b  = blockIdx.y;
    {
        int c = t & 127, half = t >> 7;
        float s = 0.f;
        for (int pc = half * 49; pc < half * 49 + 49; pc++)
            s += psum[((size_t)b * 98 + pc) * 128 + c];
        spart[half][c] = s;
    }
    __syncthreads();
    if (t < 128) sm[t] = (spart[0][t] + spart[1][t]) * (1.f / (float)PPOS);
    __syncthreads();
    if (t < 32) {
        float acc = 0.f;
        #pragma unroll 4
        for (int c = 0; c < 128; c++) acc = fmaf(sm[c], fc1[t * 128 + c], acc);
        t1[t] = fmaxf(acc, 0.f);
    }
    __syncthreads();
    if (t < 128) {
        float acc = 0.f;
        #pragma unroll
        for (int i = 0; i < 32; i++) acc = fmaf(t1[i], fc2[t * 32 + i], acc);
        satn[t] = 1.f / (1.f + __expf(-acc));
    }
    {
        int c = t & 127, ph = t >> 7;
        #pragma unroll
        for (int pass = 0; pass < 16; pass++) {
            int pl = pass * 2 + ph;
            sf[c][pl] = fused[((size_t)(b * PPOS + p0 + pl)) * 128 + c];
        }
    }
    __syncthreads();
    int pl = t & 31, c8 = t >> 5;
    #pragma unroll
    for (int pass = 0; pass < 16; pass++) {
        int c = pass * 8 + c8;
        size_t gi = ((size_t)(b * 128 + c)) * PPOS + p0 + pl;
        out[gi] = sf[c][pl] * satn[c] + x[gi];
    }
}

// ============================================================================
extern "C" void kernel_launch(void* const* d_in, const int* in_sizes, int n_in,
                              void* d_out, int out_size)
{
    const float* x       = (const float*)d_in[0];
    const float* norm_hw = (const float*)d_in[1];
    const float* norm_hb = (const float*)d_in[2];
    const float* norm_vw = (const float*)d_in[3];
    const float* norm_vb = (const float*)d_in[4];
    const float* dw_w    = (const float*)d_in[5];
    const float* dw_b    = (const float*)d_in[6];
    const float* pw_w    = (const float*)d_in[7];
    const float* pw_b    = (const float*)d_in[8];
    const float* in_w0    = (const float*)d_in[9];
    const float* conv_w0  = (const float*)d_in[10];
    const float* conv_b0  = (const float*)d_in[11];
    const float* xproj_w0 = (const float*)d_in[12];
    const float* dt_w0    = (const float*)d_in[13];
    const float* dt_b0    = (const float*)d_in[14];
    const float* A_log0   = (const float*)d_in[15];
    const float* D0       = (const float*)d_in[16];
    const float* out_w0   = (const float*)d_in[17];
    const float* in_w1    = (const float*)d_in[18];
    const float* conv_w1  = (const float*)d_in[19];
    const float* conv_b1  = (const float*)d_in[20];
    const float* xproj_w1 = (const float*)d_in[21];
    const float* dt_w1    = (const float*)d_in[22];
    const float* dt_b1    = (const float*)d_in[23];
    const float* A_log1   = (const float*)d_in[24];
    const float* D1       = (const float*)d_in[25];
    const float* out_w1   = (const float*)d_in[26];
    const float* fc1     = (const float*)d_in[27];
    const float* fc2     = (const float*)d_in[28];

    void* p;
    cudaGetSymbolAddress(&p, g_xnorm); float* xnorm = (float*)p;
    cudaGetSymbolAddress(&p, g_xz);    float* xz    = (float*)p;
    cudaGetSymbolAddress(&p, g_xs);    float* xs    = (float*)p;
    cudaGetSymbolAddress(&p, g_dbl);   float* dbl   = (float*)p;
    cudaGetSymbolAddress(&p, g_ys);    float* ys    = (float*)p;
    cudaGetSymbolAddress(&p, g_o);     float* ob    = (float*)p;
    cudaGetSymbolAddress(&p, g_g);     float* gbuf  = (float*)p;
    cudaGetSymbolAddress(&p, g_lf);    float* lfb   = (float*)p;
    cudaGetSymbolAddress(&p, g_fused); float* fused = (float*)p;
    cudaGetSymbolAddress(&p, g_Pc);    float* Pc    = (float*)p;
    cudaGetSymbolAddress(&p, g_Hc);    float* Hc    = (float*)p;
    cudaGetSymbolAddress(&p, g_Hi);    float* Hi    = (float*)p;
    cudaGetSymbolAddress(&p, g_psum);  float* psum  = (float*)p;

    // prep: layernorm (both layouts) + local-feature dwconv+gelu
    prep_kernel<<<dim3(98, 2), 256>>>(x, norm_hw, norm_hb, norm_vw, norm_vb,
                                      dw_w, dw_b,
                                      xnorm, xnorm + (size_t)MR * CDIM, gbuf);
    // in_proj (z<2) + pointwise conv (z=2), all TF32, one launch
    gemm_tf32_multi<<<dim3(4, 49, 3), 256>>>(xnorm, in_w0, in_w1, xz,
                                             gbuf, pw_w, pw_b, lfb);
    // conv + silu (rolling window, 8 pos/thread)
    conv_silu<<<dim3((MR / 8) * 64 / 256, 2), 256>>>(xz, conv_w0, conv_w1,
                                                     conv_b0, conv_b1, xs);
    // x_proj: TF32, M-tile=64, 196 blocks
    xproj_tf32<<<dim3(1, 98, 2), 256>>>(xs, xproj_w0, xproj_w1, dbl);
    // selective scan (dt inline)
    scanA<<<dim3(NC, BATCH, 2), 256>>>(xs, dbl, A_log0, A_log1,
                                       dt_w0, dt_w1, dt_b0, dt_b1, Pc, Hc);
    scanB<<<dim3(32, 2), 256>>>(Pc, Hc, Hi);
    scanC<<<dim3(NC, BATCH, 2), 256>>>(xs, dbl, xz, A_log0, A_log1,
                                       dt_w0, dt_w1, dt_b0, dt_b1, D0, D1, Hi, ys);
    // out_proj: TF32 tensor cores, 128x128 tiles, 98 blocks
    gemm_tf32<<<dim3(1, 49, 2), 256>>>(ys, out_w0, out_w1, nullptr, ob,
                                       128, 256, (size_t)MR * DI, (size_t)MR * CDIM);
    // fuse + attention + residual
    fuse_kernel<<<dim3(98, 2), 128>>>(ob, ob + (size_t)MR * CDIM, lfb, fused, psum);
    final_attn<<<dim3(98, 2), 256>>>(psum, fc1, fc2, fused, x, (float*)d_out);
}

// round 16
// speedup vs baseline: 1.0619x; 1.0180x over previous
#include <cuda_runtime.h>
#include <cuda_bf16.h>
#include <cstddef>
#include <cstdint>

#define BATCH 2
#define CDIM  128
#define HH    56
#define WWD   56
#define PPOS  3136
#define LSEQ  3136
#define MR    6272
#define DI    256
#define DS    16
#define NC    49
#define CL    64

// ---------------- scratch ----------------
__device__ __align__(16) float g_xnorm[2][MR * CDIM];
__device__ __align__(16) float g_xz   [2][MR * 512];
__device__ __align__(16) float g_xs   [2][MR * DI];
__device__ __align__(16) float g_dbl  [2][MR * 40];
__device__ __align__(16) float g_ys   [2][MR * DI];
__device__ __align__(16) float g_o    [2][MR * CDIM];
__device__ __align__(16) float g_g    [MR * CDIM];
__device__ __align__(16) float g_lf   [MR * CDIM];
__device__ __align__(16) float g_fused[MR * CDIM];
__device__ __align__(16) float g_Pc [2][NC * BATCH * DI * DS];
__device__ __align__(16) float g_Hc [2][NC * BATCH * DI * DS];
__device__ __align__(16) float g_Hi [2][NC * BATCH * DI * DS];
__device__ __align__(16) float g_psum[BATCH * 98 * CDIM];

__device__ __forceinline__ float to_tf32(float x) {
    unsigned int u;
    asm("cvt.rna.tf32.f32 %0, %1;" : "=r"(u) : "f"(x));
    return __uint_as_float(u);
}

// ========== prep: LayerNorm (both layouts) + depthwise 3x3 + GELU ==========
__global__ __launch_bounds__(256) void prep_kernel(
    const float* __restrict__ x,
    const float* __restrict__ hw, const float* __restrict__ hb,
    const float* __restrict__ vw, const float* __restrict__ vb,
    const float* __restrict__ dww, const float* __restrict__ dwb,
    float* __restrict__ xh, float* __restrict__ xv, float* __restrict__ g)
{
    __shared__ float sx[128][33];
    __shared__ float part[8][33];
    __shared__ float partq[8][33];
    __shared__ float mu[32], rs[32];
    __shared__ float sg[128][33];
    int t = threadIdx.x;
    int p0 = blockIdx.x * 32;
    int b  = blockIdx.y;
    int pl = t & 31, c8 = t >> 5;
    float s = 0.f, sq = 0.f;
    #pragma unroll
    for (int pass = 0; pass < 16; pass++) {
        int c = pass * 8 + c8;
        float v = x[((size_t)(b * 128 + c)) * PPOS + p0 + pl];
        sx[c][pl] = v;
        s += v; sq += v * v;
    }
    part[c8][pl] = s; partq[c8][pl] = sq;
    __syncthreads();
    if (t < 32) {
        float S = 0.f, Q = 0.f;
        #pragma unroll
        for (int r = 0; r < 8; r++) { S += part[r][t]; Q += partq[r][t]; }
        float mean = S * (1.f / 128.f);
        float var  = Q * (1.f / 128.f) - mean * mean;
        mu[t] = mean;
        rs[t] = rsqrtf(var + 1e-5f);
    }
    __syncthreads();
    {
        int c = t & 127, ph = t >> 7;
        float whh = hw[c], bhh = hb[c], wvv = vw[c], bvv = vb[c];
        #pragma unroll
        for (int pass = 0; pass < 16; pass++) {
            int pl2 = pass * 2 + ph;
            int p = p0 + pl2;
            float xc = (sx[c][pl2] - mu[pl2]) * rs[pl2];
            int h = p / WWD, w = p % WWD;
            xh[((size_t)b * LSEQ + p) * 128 + c]            = xc * whh + bhh;
            xv[((size_t)b * LSEQ + (w * HH + h)) * 128 + c] = xc * wvv + bvv;
        }
    }
    {
        int p = p0 + pl;
        int h = p / WWD, w = p % WWD;
        #pragma unroll
        for (int pass = 0; pass < 16; pass++) {
            int c = pass * 8 + c8;
            const float* xb = x + ((size_t)(b * 128 + c)) * PPOS;
            float acc = dwb[c];
            #pragma unroll
            for (int kh = 0; kh < 3; kh++) {
                int hh = h + kh - 1;
                if (hh < 0 || hh >= HH) continue;
                #pragma unroll
                for (int kw = 0; kw < 3; kw++) {
                    int ww = w + kw - 1;
                    if (ww < 0 || ww >= WWD) continue;
                    acc = fmaf(xb[hh * WWD + ww], dww[c * 9 + kh * 3 + kw], acc);
                }
            }
            sg[c][pl] = 0.5f * acc * (1.f + erff(acc * 0.70710678118654752f));
        }
    }
    __syncthreads();
    {
        int c = t & 127, ph = t >> 7;
        #pragma unroll
        for (int pass = 0; pass < 16; pass++) {
            int pl2 = pass * 2 + ph;
            g[((size_t)(b * PPOS + p0 + pl2)) * 128 + c] = sg[c][pl2];
        }
    }
}

// ========== TF32 GEMM core (device func): 128x128 block, 8 warps ==========
__device__ __forceinline__ void gemm_tf32_body(
    const float* __restrict__ A, const float* __restrict__ Bw,
    const float* __restrict__ bias, float* __restrict__ C,
    int m0, int n0, int N, int K)
{
    __shared__ float As[2][8][136];
    __shared__ float Bs[2][8][136];

    const int t    = threadIdx.x;
    const int lane = t & 31;
    const int wid  = t >> 5;
    const int g    = lane >> 2;
    const int tig  = lane & 3;
    const int wm   = (wid & 1) * 64;
    const int wn   = (wid >> 1) * 32;

    const int lRow = t >> 1;
    const int lK   = (t & 1) * 4;

    const float* Aptr = A + (size_t)(m0 + lRow) * K + lK;
    const float* Bptr = Bw + (size_t)(n0 + lRow) * K + lK;

    float4 pa = *(const float4*)Aptr;
    float4 pb = *(const float4*)Bptr;

    float acc[4][4][4];
    #pragma unroll
    for (int mi = 0; mi < 4; mi++)
        #pragma unroll
        for (int ni = 0; ni < 4; ni++)
            #pragma unroll
            for (int r = 0; r < 4; r++) acc[mi][ni][r] = 0.f;

    As[0][lK + 0][lRow] = to_tf32(pa.x); As[0][lK + 1][lRow] = to_tf32(pa.y);
    As[0][lK + 2][lRow] = to_tf32(pa.z); As[0][lK + 3][lRow] = to_tf32(pa.w);
    Bs[0][lK + 0][lRow] = to_tf32(pb.x); Bs[0][lK + 1][lRow] = to_tf32(pb.y);
    Bs[0][lK + 2][lRow] = to_tf32(pb.z); Bs[0][lK + 3][lRow] = to_tf32(pb.w);
    __syncthreads();

    const int nt = K >> 3;
    int buf = 0;
    for (int kt = 0; kt < nt; kt++) {
        bool more = (kt + 1 < nt);
        if (more) {
            pa = *(const float4*)(Aptr + (kt + 1) * 8);
            pb = *(const float4*)(Bptr + (kt + 1) * 8);
        }
        unsigned int af[4][4], bf[4][2];
        #pragma unroll
        for (int mi = 0; mi < 4; mi++) {
            int rm = wm + mi * 16 + g;
            af[mi][0] = __float_as_uint(As[buf][tig][rm]);
            af[mi][1] = __float_as_uint(As[buf][tig][rm + 8]);
            af[mi][2] = __float_as_uint(As[buf][tig + 4][rm]);
            af[mi][3] = __float_as_uint(As[buf][tig + 4][rm + 8]);
        }
        #pragma unroll
        for (int ni = 0; ni < 4; ni++) {
            int cn = wn + ni * 8 + g;
            bf[ni][0] = __float_as_uint(Bs[buf][tig][cn]);
            bf[ni][1] = __float_as_uint(Bs[buf][tig + 4][cn]);
        }
        #pragma unroll
        for (int mi = 0; mi < 4; mi++)
            #pragma unroll
            for (int ni = 0; ni < 4; ni++) {
                asm volatile(
                    "mma.sync.aligned.m16n8k8.row.col.f32.tf32.tf32.f32 "
                    "{%0,%1,%2,%3}, {%4,%5,%6,%7}, {%8,%9}, {%0,%1,%2,%3};\n"
                    : "+f"(acc[mi][ni][0]), "+f"(acc[mi][ni][1]),
                      "+f"(acc[mi][ni][2]), "+f"(acc[mi][ni][3])
                    : "r"(af[mi][0]), "r"(af[mi][1]), "r"(af[mi][2]), "r"(af[mi][3]),
                      "r"(bf[ni][0]), "r"(bf[ni][1]));
            }
        if (more) {
            int nb = buf ^ 1;
            As[nb][lK + 0][lRow] = to_tf32(pa.x); As[nb][lK + 1][lRow] = to_tf32(pa.y);
            As[nb][lK + 2][lRow] = to_tf32(pa.z); As[nb][lK + 3][lRow] = to_tf32(pa.w);
            Bs[nb][lK + 0][lRow] = to_tf32(pb.x); Bs[nb][lK + 1][lRow] = to_tf32(pb.y);
            Bs[nb][lK + 2][lRow] = to_tf32(pb.z); Bs[nb][lK + 3][lRow] = to_tf32(pb.w);
        }
        __syncthreads();
        buf ^= 1;
    }

    #pragma unroll
    for (int mi = 0; mi < 4; mi++) {
        int r0 = m0 + wm + mi * 16 + g;
        #pragma unroll
        for (int ni = 0; ni < 4; ni++) {
            int cc = n0 + wn + ni * 8 + 2 * tig;
            float2 bb = make_float2(0.f, 0.f);
            if (bias) bb = *(const float2*)(bias + cc);
            float2 v0 = make_float2(acc[mi][ni][0] + bb.x, acc[mi][ni][1] + bb.y);
            float2 v1 = make_float2(acc[mi][ni][2] + bb.x, acc[mi][ni][3] + bb.y);
            *(float2*)(C + (size_t)r0 * N + cc)       = v0;
            *(float2*)(C + (size_t)(r0 + 8) * N + cc) = v1;
        }
    }
}

// generic TF32 GEMM (used for out_proj)
__global__ __launch_bounds__(256) void gemm_tf32(
    const float* __restrict__ Abase,
    const float* __restrict__ B0, const float* __restrict__ B1,
    const float* __restrict__ bias,
    float* __restrict__ Cbase,
    int N, int K, size_t dsA, size_t dsC)
{
    const int dir = blockIdx.z;
    gemm_tf32_body(Abase + (size_t)dir * dsA, dir ? B1 : B0, bias,
                   Cbase + (size_t)dir * dsC,
                   blockIdx.y * 128, blockIdx.x * 128, N, K);
}

// merged: z<2 -> in_proj (N=512,K=128), z==2 -> pointwise conv (N=128,K=128)
__global__ __launch_bounds__(256) void gemm_tf32_multi(
    const float* __restrict__ xnorm,
    const float* __restrict__ inw0, const float* __restrict__ inw1,
    float* __restrict__ xz,
    const float* __restrict__ gbuf, const float* __restrict__ pww,
    const float* __restrict__ pwb, float* __restrict__ lfb)
{
    const int z = blockIdx.z;
    if (z < 2) {
        gemm_tf32_body(xnorm + (size_t)z * MR * CDIM, z ? inw1 : inw0, nullptr,
                       xz + (size_t)z * MR * 512,
                       blockIdx.y * 128, blockIdx.x * 128, 512, 128);
    } else {
        if (blockIdx.x != 0) return;
        gemm_tf32_body(gbuf, pww, pwb, lfb, blockIdx.y * 128, 0, 128, 128);
    }
}

// ========== x_proj GEMM via TF32: M-tile=32, BK=16, 392 blocks ==========
// 8 warps as 2(M)x4(N); warp tile m16 x n16; acc[2][4] per thread.
__global__ __launch_bounds__(256) void xproj_tf32(
    const float* __restrict__ xsg,
    const float* __restrict__ W0, const float* __restrict__ W1,
    float* __restrict__ dblg)
{
    const int dir = blockIdx.z;
    const float* A  = xsg + (size_t)dir * MR * DI;
    const float* Bw = dir ? W1 : W0;
    float* C = dblg + (size_t)dir * MR * 40;
    const int m0 = blockIdx.y * 32;
    const int K = 256;

    __shared__ float As[2][16][40];   // 40 mod 32 == 8 -> conflict-free frag loads
    __shared__ float Bs[2][16][72];   // 72 mod 32 == 8

    const int t    = threadIdx.x;
    const int lane = t & 31;
    const int wid  = t >> 5;
    const int g    = lane >> 2;
    const int tig  = lane & 3;
    const int wm   = (wid & 1) * 16;   // 0,16
    const int wn   = (wid >> 1) * 16;  // 0,16,32,48

    // A loader: 32 rows x 16 k = 512 floats; 128 threads x float4
    const bool aAct = t < 128;
    const int aRow = t & 31;
    const int aK   = (t >> 5) * 4;     // 0,4,8,12 for t<128
    // B loader: 40 rows x 16 k = 640 floats; 160 threads x float4
    const int bRow = t >> 2;
    const int bK   = (t & 3) * 4;
    const bool bAct = bRow < 40;

    const float* Aptr = A + (size_t)(m0 + aRow) * K + (aAct ? aK : 0);
    const float* Bptr = Bw + (size_t)(bAct ? bRow : 0) * K + bK;

    float4 pa = aAct ? *(const float4*)Aptr : make_float4(0.f, 0.f, 0.f, 0.f);
    float4 pb = bAct ? *(const float4*)Bptr : make_float4(0.f, 0.f, 0.f, 0.f);

    float acc[2][4];
    #pragma unroll
    for (int ni = 0; ni < 2; ni++)
        #pragma unroll
        for (int r = 0; r < 4; r++) acc[ni][r] = 0.f;

    if (aAct) {
        As[0][aK + 0][aRow] = to_tf32(pa.x); As[0][aK + 1][aRow] = to_tf32(pa.y);
        As[0][aK + 2][aRow] = to_tf32(pa.z); As[0][aK + 3][aRow] = to_tf32(pa.w);
    }
    if (bAct) {
        Bs[0][bK + 0][bRow] = to_tf32(pb.x); Bs[0][bK + 1][bRow] = to_tf32(pb.y);
        Bs[0][bK + 2][bRow] = to_tf32(pb.z); Bs[0][bK + 3][bRow] = to_tf32(pb.w);
    }
    __syncthreads();

    int buf = 0;
    for (int kt = 0; kt < 16; kt++) {            // 16 tiles of BK=16
        bool more = (kt + 1 < 16);
        if (more) {
            if (aAct) pa = *(const float4*)(Aptr + (kt + 1) * 16);
            if (bAct) pb = *(const float4*)(Bptr + (kt + 1) * 16);
        }
        #pragma unroll
        for (int ks = 0; ks < 2; ks++) {         // two k=8 steps per tile
            int k0 = ks * 8;
            unsigned int af[4], bf[2][2];
            {
                int rm = wm + g;
                af[0] = __float_as_uint(As[buf][k0 + tig][rm]);
                af[1] = __float_as_uint(As[buf][k0 + tig][rm + 8]);
                af[2] = __float_as_uint(As[buf][k0 + tig + 4][rm]);
                af[3] = __float_as_uint(As[buf][k0 + tig + 4][rm + 8]);
            }
            #pragma unroll
            for (int ni = 0; ni < 2; ni++) {
                int cn = wn + ni * 8 + g;
                bf[ni][0] = __float_as_uint(Bs[buf][k0 + tig][cn]);
                bf[ni][1] = __float_as_uint(Bs[buf][k0 + tig + 4][cn]);
            }
            #pragma unroll
            for (int ni = 0; ni < 2; ni++) {
                asm volatile(
                    "mma.sync.aligned.m16n8k8.row.col.f32.tf32.tf32.f32 "
                    "{%0,%1,%2,%3}, {%4,%5,%6,%7}, {%8,%9}, {%0,%1,%2,%3};\n"
                    : "+f"(acc[ni][0]), "+f"(acc[ni][1]),
                      "+f"(acc[ni][2]), "+f"(acc[ni][3])
                    : "r"(af[0]), "r"(af[1]), "r"(af[2]), "r"(af[3]),
                      "r"(bf[ni][0]), "r"(bf[ni][1]));
            }
        }
        if (more) {
            int nb = buf ^ 1;
            if (aAct) {
                As[nb][aK + 0][aRow] = to_tf32(pa.x); As[nb][aK + 1][aRow] = to_tf32(pa.y);
                As[nb][aK + 2][aRow] = to_tf32(pa.z); As[nb][aK + 3][aRow] = to_tf32(pa.w);
            }
            if (bAct) {
                Bs[nb][bK + 0][bRow] = to_tf32(pb.x); Bs[nb][bK + 1][bRow] = to_tf32(pb.y);
                Bs[nb][bK + 2][bRow] = to_tf32(pb.z); Bs[nb][bK + 3][bRow] = to_tf32(pb.w);
            }
        }
        __syncthreads();
        buf ^= 1;
    }

    int r0 = m0 + wm + g;
    #pragma unroll
    for (int ni = 0; ni < 2; ni++) {
        int cc = wn + ni * 8 + 2 * tig;
        if (cc >= 40) continue;
        float2 v0 = make_float2(acc[ni][0], acc[ni][1]);
        float2 v1 = make_float2(acc[ni][2], acc[ni][3]);
        *(float2*)(C + (size_t)r0 * 40 + cc)       = v0;
        *(float2*)(C + (size_t)(r0 + 8) * 40 + cc) = v1;
    }
}

// ========== causal conv1d k=4 + silu, rolling window: 8 positions/thread ====
__global__ __launch_bounds__(256) void conv_silu(
    const float* __restrict__ xzg,
    const float* __restrict__ cw0, const float* __restrict__ cw1,
    const float* __restrict__ cb0, const float* __restrict__ cb1,
    float* __restrict__ xsg)
{
    const int dir = blockIdx.y;
    const float* xz = xzg + (size_t)dir * MR * 512;
    const float* cw = dir ? cw1 : cw0;
    const float* cb = dir ? cb1 : cb0;
    float* xs = xsg + (size_t)dir * MR * DI;
    int idx = blockIdx.x * 256 + threadIdx.x;
    if (idx >= (MR / 8) * 64) return;
    int d4 = idx & 63;
    int mt = idx >> 6;
    int m0 = mt * 8;
    int l0 = m0 % LSEQ;
    int d  = d4 * 4;
    float4 bias = *(const float4*)(cb + d);
    float4 wk[4];
    #pragma unroll
    for (int k = 0; k < 4; k++) {
        wk[k].x = cw[(d + 0) * 4 + k];
        wk[k].y = cw[(d + 1) * 4 + k];
        wk[k].z = cw[(d + 2) * 4 + k];
        wk[k].w = cw[(d + 3) * 4 + k];
    }
    const float4 zero = make_float4(0.f, 0.f, 0.f, 0.f);
    float4 r0 = (l0 >= 3) ? *(const float4*)(xz + (size_t)(m0 - 3) * 512 + d) : zero;
    float4 r1 = (l0 >= 2) ? *(const float4*)(xz + (size_t)(m0 - 2) * 512 + d) : zero;
    float4 r2 = (l0 >= 1) ? *(const float4*)(xz + (size_t)(m0 - 1) * 512 + d) : zero;
    #pragma unroll
    for (int tt = 0; tt < 8; tt++) {
        float4 cur = *(const float4*)(xz + (size_t)(m0 + tt) * 512 + d);
        float4 a = bias;
        a.x = fmaf(r0.x, wk[0].x, a.x); a.y = fmaf(r0.y, wk[0].y, a.y);
        a.z = fmaf(r0.z, wk[0].z, a.z); a.w = fmaf(r0.w, wk[0].w, a.w);
        a.x = fmaf(r1.x, wk[1].x, a.x); a.y = fmaf(r1.y, wk[1].y, a.y);
        a.z = fmaf(r1.z, wk[1].z, a.z); a.w = fmaf(r1.w, wk[1].w, a.w);
        a.x = fmaf(r2.x, wk[2].x, a.x); a.y = fmaf(r2.y, wk[2].y, a.y);
        a.z = fmaf(r2.z, wk[2].z, a.z); a.w = fmaf(r2.w, wk[2].w, a.w);
        a.x = fmaf(cur.x, wk[3].x, a.x); a.y = fmaf(cur.y, wk[3].y, a.y);
        a.z = fmaf(cur.z, wk[3].z, a.z); a.w = fmaf(cur.w, wk[3].w, a.w);
        float4 o;
        o.x = a.x / (1.f + __expf(-a.x));
        o.y = a.y / (1.f + __expf(-a.y));
        o.z = a.z / (1.f + __expf(-a.z));
        o.w = a.w / (1.f + __expf(-a.w));
        *(float4*)(xs + (size_t)(m0 + tt) * DI + d) = o;
        r0 = r1; r1 = r2; r2 = cur;
    }
}

// ========== scan pass A (dt computed inline from dbl) ==========
__global__ __launch_bounds__(256) void scanA(
    const float* __restrict__ xsg, const float* __restrict__ dblg,
    const float* __restrict__ Al0, const float* __restrict__ Al1,
    const float* __restrict__ dtw0, const float* __restrict__ dtw1,
    const float* __restrict__ dtb0, const float* __restrict__ dtb1,
    float* __restrict__ Pcg, float* __restrict__ Hcg)
{
    int d = threadIdx.x, chunk = blockIdx.x, b = blockIdx.y, dir = blockIdx.z;
    const float* xs  = xsg + (size_t)dir * MR * DI;
    const float* dbl = dblg + (size_t)dir * MR * 40;
    const float* Al  = dir ? Al1 : Al0;
    const float* dtw = dir ? dtw1 : dtw0;
    const float* dtb = dir ? dtb1 : dtb0;
    float* Pc = Pcg + (size_t)dir * NC * BATCH * DI * DS;
    float* Hc = Hcg + (size_t)dir * NC * BATCH * DI * DS;
    __shared__ float sB[CL][24];
    int base = b * LSEQ + chunk * CL;
    for (int i = d; i < CL * 24; i += 256) {
        int l = i / 24, n = i % 24;
        sB[l][n] = dbl[(size_t)(base + l) * 40 + n];
    }
    float a[16]; bool fast = true;
    #pragma unroll
    for (int n = 0; n < 16; n++) {
        a[n] = -__expf(Al[d * 16 + n]);
        fast = fast && (fabsf(a[n] + (float)(n + 1)) <= 1e-4f * (n + 1));
    }
    float w[8];
    #pragma unroll
    for (int r = 0; r < 8; r++) w[r] = dtw[d * 8 + r];
    float db = dtb[d];
    __syncthreads();
    float h[16], pp[16];
    #pragma unroll
    for (int n = 0; n < 16; n++) { h[n] = 0.f; pp[n] = 1.f; }
    if (fast) {
        for (int l = 0; l < CL; l++) {
            float s = db;
            #pragma unroll
            for (int r = 0; r < 8; r++) s = fmaf(sB[l][r], w[r], s);
            float dtv = (s > 20.f) ? s : __logf(1.f + __expf(s));
            float xsv = xs[(size_t)(base + l) * DI + d];
            float du = dtv * xsv;
            float e1 = __expf(-dtv);
            float e[16]; e[0] = e1;
            #pragma unroll
            for (int n = 1; n < 16; n++) e[n] = e[n - 1] * e1;
            #pragma unroll
            for (int n = 0; n < 16; n++) {
                pp[n] *= e[n];
                h[n] = fmaf(e[n], h[n], du * sB[l][8 + n]);
            }
        }
    } else {
        for (int l = 0; l < CL; l++) {
            float s = db;
            #pragma unroll
            for (int r = 0; r < 8; r++) s = fmaf(sB[l][r], w[r], s);
            float dtv = (s > 20.f) ? s : __logf(1.f + __expf(s));
            float xsv = xs[(size_t)(base + l) * DI + d];
            float du = dtv * xsv;
            #pragma unroll
            for (int n = 0; n < 16; n++) {
                float e = __expf(dtv * a[n]);
                pp[n] *= e;
                h[n] = fmaf(e, h[n], du * sB[l][8 + n]);
            }
        }
    }
    size_t o = (((size_t)chunk * BATCH + b) * DI + d) * DS;
    #pragma unroll
    for (int n = 0; n < 16; n++) { Pc[o + n] = pp[n]; Hc[o + n] = h[n]; }
}

// ========== scan pass B ==========
__global__ void scanB(const float* __restrict__ Pcg, const float* __restrict__ Hcg,
                      float* __restrict__ Hig)
{
    int dir = blockIdx.y;
    const float* Pc = Pcg + (size_t)dir * NC * BATCH * DI * DS;
    const float* Hc = Hcg + (size_t)dir * NC * BATCH * DI * DS;
    float* Hi = Hig + (size_t)dir * NC * BATCH * DI * DS;
    int idx = blockIdx.x * 256 + threadIdx.x;
    if (idx >= BATCH * DI * DS) return;
    float h = 0.f;
    for (int c = 0; c < NC; c++) {
        size_t o = (size_t)c * (BATCH * DI * DS) + idx;
        Hi[o] = h;
        h = fmaf(Pc[o], h, Hc[o]);
    }
}

// ========== scan pass C + gate fused (dt inline) ==========
__global__ __launch_bounds__(256) void scanC(
    const float* __restrict__ xsg, const float* __restrict__ dblg,
    const float* __restrict__ xzg,
    const float* __restrict__ Al0, const float* __restrict__ Al1,
    const float* __restrict__ dtw0, const float* __restrict__ dtw1,
    const float* __restrict__ dtb0, const float* __restrict__ dtb1,
    const float* __restrict__ D0, const float* __restrict__ D1,
    const float* __restrict__ Hig, float* __restrict__ ysg)
{
    int d = threadIdx.x, chunk = blockIdx.x, b = blockIdx.y, dir = blockIdx.z;
    const float* xs  = xsg + (size_t)dir * MR * DI;
    const float* dbl = dblg + (size_t)dir * MR * 40;
    const float* xz  = xzg + (size_t)dir * MR * 512;
    const float* Al  = dir ? Al1 : Al0;
    const float* dtw = dir ? dtw1 : dtw0;
    const float* dtb = dir ? dtb1 : dtb0;
    const float* Dp  = dir ? D1 : D0;
    const float* Hi  = Hig + (size_t)dir * NC * BATCH * DI * DS;
    float* ys = ysg + (size_t)dir * MR * DI;
    __shared__ float sBC[CL][40];
    int base = b * LSEQ + chunk * CL;
    for (int i = d; i < CL * 40; i += 256) {
        int l = i / 40, j = i % 40;
        sBC[l][j] = dbl[(size_t)(base + l) * 40 + j];
    }
    float a[16]; bool fast = true;
    #pragma unroll
    for (int n = 0; n < 16; n++) {
        a[n] = -__expf(Al[d * 16 + n]);
        fast = fast && (fabsf(a[n] + (float)(n + 1)) <= 1e-4f * (n + 1));
    }
    float w[8];
    #pragma unroll
    for (int r = 0; r < 8; r++) w[r] = dtw[d * 8 + r];
    float db = dtb[d];
    float Dd = Dp[d];
    float h[16];
    size_t o = (((size_t)chunk * BATCH + b) * DI + d) * DS;
    #pragma unroll
    for (int n = 0; n < 16; n++) h[n] = Hi[o + n];
    __syncthreads();
    if (fast) {
        for (int l = 0; l < CL; l++) {
            float s = db;
            #pragma unroll
            for (int r = 0; r < 8; r++) s = fmaf(sBC[l][r], w[r], s);
            float dtv = (s > 20.f) ? s : __logf(1.f + __expf(s));
            float xsv = xs[(size_t)(base + l) * DI + d];
            float zv  = xz[(size_t)(base + l) * 512 + 256 + d];
            float du = dtv * xsv;
            float e1 = __expf(-dtv);
            float e[16]; e[0] = e1;
            #pragma unroll
            for (int n = 1; n < 16; n++) e[n] = e[n - 1] * e1;
            float y = 0.f;
            #pragma unroll
            for (int n = 0; n < 16; n++) {
                h[n] = fmaf(e[n], h[n], du * sBC[l][8 + n]);
                y = fmaf(h[n], sBC[l][24 + n], y);
            }
            float sz = zv / (1.f + __expf(-zv));
            ys[(size_t)(base + l) * DI + d] = (y + xsv * Dd) * sz;
        }
    } else {
        for (int l = 0; l < CL; l++) {
            float s = db;
            #pragma unroll
            for (int r = 0; r < 8; r++) s = fmaf(sBC[l][r], w[r], s);
            float dtv = (s > 20.f) ? s : __logf(1.f + __expf(s));
            float xsv = xs[(size_t)(base + l) * DI + d];
            float zv  = xz[(size_t)(base + l) * 512 + 256 + d];
            float du = dtv * xsv;
            float y = 0.f;
            #pragma unroll
            for (int n = 0; n < 16; n++) {
                float e = __expf(dtv * a[n]);
                h[n] = fmaf(e, h[n], du * sBC[l][8 + n]);
                y = fmaf(h[n], sBC[l][24 + n], y);
            }
            float sz = zv / (1.f + __expf(-zv));
            ys[(size_t)(base + l) * DI + d] = (y + xsv * Dd) * sz;
        }
    }
}

// ========== fuse oh+ov+lf, partial sums ==========
__global__ void fuse_kernel(const float* __restrict__ oh, const float* __restrict__ ov,
                            const float* __restrict__ lf, float* __restrict__ fused,
                            float* __restrict__ psum)
{
    int c = threadIdx.x;
    int pc = blockIdx.x;
    int b  = blockIdx.y;
    float s = 0.f;
    for (int i = 0; i < 32; i++) {
        int p = pc * 32 + i;
        int pv = (p % WWD) * HH + p / WWD;
        float f = oh[((size_t)(b * LSEQ + p)) * 128 + c]
                + ov[((size_t)(b * LSEQ + pv)) * 128 + c]
                + lf[((size_t)(b * PPOS + p)) * 128 + c];
        fused[((size_t)(b * PPOS + p)) * 128 + c] = f;
        s += f;
    }
    psum[((size_t)b * 98 + pc) * 128 + c] = s;
}

// ========== final: channel attention (recomputed per block) + residual ==========
__global__ __launch_bounds__(256) void final_attn(
    const float* __restrict__ psum,
    const float* __restrict__ fc1, const float* __restrict__ fc2,
    const float* __restrict__ fused, const float* __restrict__ x,
    float* __restrict__ out)
{
    __shared__ float spart[2][128];
    __shared__ float sm[128];
    __shared__ float t1[32];
    __shared__ float satn[128];
    __shared__ float sf[128][33];
    int t = threadIdx.x;
    int p0 = blockIdx.x * 32;
    int b  = blockIdx.y;
    {
        int c = t & 127, half = t >> 7;
        float s = 0.f;
        for (int pc = half * 49; pc < half * 49 + 49; pc++)
            s += psum[((size_t)b * 98 + pc) * 128 + c];
        spart[half][c] = s;
    }
    __syncthreads();
    if (t < 128) sm[t] = (spart[0][t] + spart[1][t]) * (1.f / (float)PPOS);
    __syncthreads();
    if (t < 32) {
        float acc = 0.f;
        #pragma unroll 4
        for (int c = 0; c < 128; c++) acc = fmaf(sm[c], fc1[t * 128 + c], acc);
        t1[t] = fmaxf(acc, 0.f);
    }
    __syncthreads();
    if (t < 128) {
        float acc = 0.f;
        #pragma unroll
        for (int i = 0; i < 32; i++) acc = fmaf(t1[i], fc2[t * 32 + i], acc);
        satn[t] = 1.f / (1.f + __expf(-acc));
    }
    {
        int c = t & 127, ph = t >> 7;
        #pragma unroll
        for (int pass = 0; pass < 16; pass++) {
            int pl = pass * 2 + ph;
            sf[c][pl] = fused[((size_t)(b * PPOS + p0 + pl)) * 128 + c];
        }
    }
    __syncthreads();
    int pl = t & 31, c8 = t >> 5;
    #pragma unroll
    for (int pass = 0; pass < 16; pass++) {
        int c = pass * 8 + c8;
        size_t gi = ((size_t)(b * 128 + c)) * PPOS + p0 + pl;
        out[gi] = sf[c][pl] * satn[c] + x[gi];
    }
}

// ============================================================================
extern "C" void kernel_launch(void* const* d_in, const int* in_sizes, int n_in,
                              void* d_out, int out_size)
{
    const float* x       = (const float*)d_in[0];
    const float* norm_hw = (const float*)d_in[1];
    const float* norm_hb = (const float*)d_in[2];
    const float* norm_vw = (const float*)d_in[3];
    const float* norm_vb = (const float*)d_in[4];
    const float* dw_w    = (const float*)d_in[5];
    const float* dw_b    = (const float*)d_in[6];
    const float* pw_w    = (const float*)d_in[7];
    const float* pw_b    = (const float*)d_in[8];
    const float* in_w0    = (const float*)d_in[9];
    const float* conv_w0  = (const float*)d_in[10];
    const float* conv_b0  = (const float*)d_in[11];
    const float* xproj_w0 = (const float*)d_in[12];
    const float* dt_w0    = (const float*)d_in[13];
    const float* dt_b0    = (const float*)d_in[14];
    const float* A_log0   = (const float*)d_in[15];
    const float* D0       = (const float*)d_in[16];
    const float* out_w0   = (const float*)d_in[17];
    const float* in_w1    = (const float*)d_in[18];
    const float* conv_w1  = (const float*)d_in[19];
    const float* conv_b1  = (const float*)d_in[20];
    const float* xproj_w1 = (const float*)d_in[21];
    const float* dt_w1    = (const float*)d_in[22];
    const float* dt_b1    = (const float*)d_in[23];
    const float* A_log1   = (const float*)d_in[24];
    const float* D1       = (const float*)d_in[25];
    const float* out_w1   = (const float*)d_in[26];
    const float* fc1     = (const float*)d_in[27];
    const float* fc2     = (const float*)d_in[28];

    void* p;
    cudaGetSymbolAddress(&p, g_xnorm); float* xnorm = (float*)p;
    cudaGetSymbolAddress(&p, g_xz);    float* xz    = (float*)p;
    cudaGetSymbolAddress(&p, g_xs);    float* xs    = (float*)p;
    cudaGetSymbolAddress(&p, g_dbl);   float* dbl   = (float*)p;
    cudaGetSymbolAddress(&p, g_ys);    float* ys    = (float*)p;
    cudaGetSymbolAddress(&p, g_o);     float* ob    = (float*)p;
    cudaGetSymbolAddress(&p, g_g);     float* gbuf  = (float*)p;
    cudaGetSymbolAddress(&p, g_lf);    float* lfb   = (float*)p;
    cudaGetSymbolAddress(&p, g_fused); float* fused = (float*)p;
    cudaGetSymbolAddress(&p, g_Pc);    float* Pc    = (float*)p;
    cudaGetSymbolAddress(&p, g_Hc);    float* Hc    = (float*)p;
    cudaGetSymbolAddress(&p, g_Hi);    float* Hi    = (float*)p;
    cudaGetSymbolAddress(&p, g_psum);  float* psum  = (float*)p;

    // prep: layernorm (both layouts) + local-feature dwconv+gelu
    prep_kernel<<<dim3(98, 2), 256>>>(x, norm_hw, norm_hb, norm_vw, norm_vb,
                                      dw_w, dw_b,
                                      xnorm, xnorm + (size_t)MR * CDIM, gbuf);
    // in_proj (z<2) + pointwise conv (z=2), all TF32, one launch
    gemm_tf32_multi<<<dim3(4, 49, 3), 256>>>(xnorm, in_w0, in_w1, xz,
                                             gbuf, pw_w, pw_b, lfb);
    // conv + silu (rolling window, 8 pos/thread)
    conv_silu<<<dim3((MR / 8) * 64 / 256, 2), 256>>>(xz, conv_w0, conv_w1,
                                                     conv_b0, conv_b1, xs);
    // x_proj: TF32, M-tile=32, BK=16, 392 blocks
    xproj_tf32<<<dim3(1, 196, 2), 256>>>(xs, xproj_w0, xproj_w1, dbl);
    // selective scan (dt inline)
    scanA<<<dim3(NC, BATCH, 2), 256>>>(xs, dbl, A_log0, A_log1,
                                       dt_w0, dt_w1, dt_b0, dt_b1, Pc, Hc);
    scanB<<<dim3(32, 2), 256>>>(Pc, Hc, Hi);
    scanC<<<dim3(NC, BATCH, 2), 256>>>(xs, dbl, xz, A_log0, A_log1,
                                       dt_w0, dt_w1, dt_b0, dt_b1, D0, D1, Hi, ys);
    // out_proj: TF32 tensor cores, 128x128 tiles, 98 blocks
    gemm_tf32<<<dim3(1, 49, 2), 256>>>(ys, out_w0, out_w1, nullptr, ob,
                                       128, 256, (size_t)MR * DI, (size_t)MR * CDIM);
    // fuse + attention + residual
    fuse_kernel<<<dim3(98, 2), 128>>>(ob, ob + (size_t)MR * CDIM, lfb, fused, psum);
    final_attn<<<dim3(98, 2), 256>>>(psum, fc1, fc2, fused, x, (float*)d_out);
}